// round 12
// baseline (speedup 1.0000x reference)
#include <cuda_runtime.h>
#include <cuda_bf16.h>
#include <mma.h>
#include <cstdint>

using namespace nvcuda;
typedef __nv_bfloat16 bf16;

#define LNUM 6
#define HNUM 12
#define DDIM 768
#define DHD  64
#define FDIM 3072
#define VOC  32000
#define SEQ  1024
#define BAT  2
#define TTOK (BAT*SEQ)
#define QKVN (3*DDIM)
#define EPS  1e-5f

// ---------------- scratch (static device globals; no allocation) ----------------
__device__ float g_x [TTOK*DDIM];
__device__ bf16 g_xnh[TTOK*DDIM],  g_xnl[TTOK*DDIM];
__device__ bf16 g_qkvh[(long long)TTOK*QKVN], g_qkvl[(long long)TTOK*QKVN];
__device__ bf16 g_aoh[TTOK*DDIM],  g_aol[TTOK*DDIM];
__device__ bf16 g_h1h[(long long)TTOK*FDIM], g_h1l[(long long)TTOK*FDIM];
__device__ float g_part[(long long)2*TTOK*FDIM];   // split-K partials (50MB)
// pre-split weights
__device__ bf16 g_wqkvh[(long long)LNUM*DDIM*QKVN], g_wqkvl[(long long)LNUM*DDIM*QKVN];
__device__ float g_bqkv[LNUM*QKVN];
__device__ bf16 g_woh[(long long)LNUM*DDIM*DDIM],  g_wol[(long long)LNUM*DDIM*DDIM];
__device__ bf16 g_w1h[(long long)LNUM*DDIM*FDIM],  g_w1l[(long long)LNUM*DDIM*FDIM];
__device__ bf16 g_w2h[(long long)LNUM*FDIM*DDIM],  g_w2l[(long long)LNUM*FDIM*DDIM];
__device__ bf16 g_embh[(long long)VOC*DDIM],       g_embl[(long long)VOC*DDIM];

// ---------------- helpers ----------------
__device__ __forceinline__ void split2(float v, bf16& h, bf16& l) {
    h = __float2bfloat16(v);
    l = __float2bfloat16(v - __bfloat162float(h));
}
__device__ __forceinline__ void cp16(bf16* dst, const bf16* src) {
    unsigned int d = (unsigned int)__cvta_generic_to_shared(dst);
    asm volatile("cp.async.cg.shared.global [%0], [%1], 16;" :: "r"(d), "l"(src));
}
__device__ __forceinline__ void cp_commit() { asm volatile("cp.async.commit_group;"); }
template<int N> __device__ __forceinline__ void cp_wait() {
    asm volatile("cp.async.wait_group %0;" :: "n"(N));
}
__device__ __forceinline__ float warp_sum(float v) {
    #pragma unroll
    for (int o = 16; o; o >>= 1) v += __shfl_xor_sync(0xffffffffu, v, o);
    return v;
}

// ---------------- weight pre-split kernels ----------------
__global__ void split_qkv_k(const float* __restrict__ src, bf16* __restrict__ hi,
                            bf16* __restrict__ lo, int coloff, float scale)
{
    long long idx = (long long)blockIdx.x * 256 + threadIdx.x;
    int kk = (int)(idx & (DHD - 1));
    long long t = idx >> 6;
    int d = (int)(t % DDIM); t /= DDIM;
    int h = (int)(t % HNUM);
    int l = (int)(t / HNUM);
    long long dst = ((long long)l * DDIM + d) * QKVN + coloff + h * DHD + kk;
    float v = src[idx] * scale;
    bf16 hh, ll; split2(v, hh, ll);
    hi[dst] = hh; lo[dst] = ll;
}

__global__ void bias_qkv_k(const float* __restrict__ bq, const float* __restrict__ bk,
                           const float* __restrict__ bv)
{
    int i = blockIdx.x * 256 + threadIdx.x;
    int col = i % QKVN, l = i / QKVN;
    float v;
    if (col < DDIM)            v = bq[l * DDIM + col] * 0.125f;
    else if (col < 2 * DDIM)   v = bk[l * DDIM + col - DDIM];
    else                       v = bv[l * DDIM + col - 2 * DDIM];
    g_bqkv[i] = v;
}

__global__ void split_plain_k(const float4* __restrict__ src, bf16* __restrict__ hi,
                              bf16* __restrict__ lo, long long n4)
{
    long long i = (long long)blockIdx.x * 256 + threadIdx.x;
    if (i >= n4) return;
    float4 v = src[i];
    bf16 h, l;
    __nv_bfloat162* h2 = (__nv_bfloat162*)hi;
    __nv_bfloat162* l2 = (__nv_bfloat162*)lo;
    __nv_bfloat162 ha, hb, la, lb;
    split2(v.x, h, l); ha.x = h; la.x = l;
    split2(v.y, h, l); ha.y = h; la.y = l;
    split2(v.z, h, l); hb.x = h; lb.x = l;
    split2(v.w, h, l); hb.y = h; lb.y = l;
    h2[2*i] = ha; h2[2*i+1] = hb;
    l2[2*i] = la; l2[2*i+1] = lb;
}

// ---------------- split-K reduction kernels ----------------
// x += p0 + p1 + bias
__global__ void reduce_resid_k(const float* __restrict__ p, float* __restrict__ xo,
                               const float* __restrict__ bias, int N, long long zoff)
{
    long long i = (long long)blockIdx.x * 256 + threadIdx.x;   // float4 index
    float4 a = ((const float4*)p)[i];
    float4 b = ((const float4*)(p + zoff))[i];
    float4 x = ((float4*)xo)[i];
    int col = (int)((i * 4) % N);
    x.x += a.x + b.x + bias[col + 0];
    x.y += a.y + b.y + bias[col + 1];
    x.z += a.z + b.z + bias[col + 2];
    x.w += a.w + b.w + bias[col + 3];
    ((float4*)xo)[i] = x;
}

// h = relu(p0 + p1 + bias) -> split bf16 hi/lo
__global__ void reduce_relu_split_k(const float* __restrict__ p,
                                    bf16* __restrict__ oh, bf16* __restrict__ ol,
                                    const float* __restrict__ bias, int N, long long zoff)
{
    long long i = (long long)blockIdx.x * 256 + threadIdx.x;   // float4 index
    float4 a = ((const float4*)p)[i];
    float4 b = ((const float4*)(p + zoff))[i];
    int col = (int)((i * 4) % N);
    float v0 = fmaxf(a.x + b.x + bias[col + 0], 0.f);
    float v1 = fmaxf(a.y + b.y + bias[col + 1], 0.f);
    float v2 = fmaxf(a.z + b.z + bias[col + 2], 0.f);
    float v3 = fmaxf(a.w + b.w + bias[col + 3], 0.f);
    bf16 h, l;
    __nv_bfloat162 ha, hb, la, lb;
    split2(v0, h, l); ha.x = h; la.x = l;
    split2(v1, h, l); ha.y = h; la.y = l;
    split2(v2, h, l); hb.x = h; lb.x = l;
    split2(v3, h, l); hb.y = h; lb.y = l;
    ((__nv_bfloat162*)oh)[2*i] = ha; ((__nv_bfloat162*)oh)[2*i+1] = hb;
    ((__nv_bfloat162*)ol)[2*i] = la; ((__nv_bfloat162*)ol)[2*i+1] = lb;
}

// ---------------- embedding ----------------
__global__ void embed_k(const int* __restrict__ X, const float* __restrict__ emb,
                        const float* __restrict__ pos, float* __restrict__ x)
{
    int t = blockIdx.x;
    int tok = X[t];
    int s = t % SEQ;
    const float* er = emb + (long long)tok * DDIM;
    const float* pr = pos + (long long)s * DDIM;
    float* xr = x + (long long)t * DDIM;
    for (int d = threadIdx.x; d < DDIM; d += blockDim.x)
        xr[d] = er[d] + pr[d];
}

// ---------------- layernorm -> split bf16 output ----------------
__global__ void ln_k(const float* __restrict__ x, const float* __restrict__ g,
                     const float* __restrict__ b, bf16* __restrict__ yh,
                     bf16* __restrict__ yl)
{
    int row = blockIdx.x;
    const float* xr = x + (long long)row * DDIM;
    bf16* yhr = yh + (long long)row * DDIM;
    bf16* ylr = yl + (long long)row * DDIM;
    int tid = threadIdx.x;

    float sum = 0.f, sq = 0.f;
    for (int i = tid; i < DDIM; i += 256) {
        float v = xr[i];
        sum += v; sq += v * v;
    }
    __shared__ float shs[8], shq[8];
    float s1 = warp_sum(sum), s2 = warp_sum(sq);
    int wid = tid >> 5, lane = tid & 31;
    if (lane == 0) { shs[wid] = s1; shq[wid] = s2; }
    __syncthreads();
    float ts = 0.f, tq = 0.f;
    #pragma unroll
    for (int w = 0; w < 8; w++) { ts += shs[w]; tq += shq[w]; }
    float mu = ts * (1.0f / DDIM);
    float var = tq * (1.0f / DDIM) - mu * mu;
    float r = rsqrtf(var + EPS);
    for (int i = tid; i < DDIM; i += 256) {
        float o = (xr[i] - mu) * r * g[i] + b[i];
        bf16 h, l; split2(o, h, l);
        yhr[i] = h; ylr[i] = l;
    }
}

// ---------------- fused causal flash attention (R9 version) ----------------
#define FBR 128
#define FBC 64
#define FLQ 72
#define FLS 68
__global__ void __launch_bounds__(256, 1) flash_k(
    const bf16* __restrict__ qkvh, const bf16* __restrict__ qkvl,
    bf16* __restrict__ aoh, bf16* __restrict__ aol)
{
    const int bh = blockIdx.x;
    const int b = bh / HNUM, h = bh - b * HNUM;
    const int m0 = (gridDim.y - 1 - blockIdx.y) * FBR;
    const int hc = h * DHD;

    extern __shared__ char smraw[];
    bf16* sQh = (bf16*)smraw;
    bf16* sQl = sQh + FBR * FLQ;
    bf16* sK  = sQl + FBR * FLQ;
    bf16* sV  = sK + 2 * 2 * FBC * FLQ;
    float* sS = (float*)(sV + 2 * 2 * FBC * FLQ);
    bf16* sPh = (bf16*)(sS + FBR * FLS);
    bf16* sPl = sPh + FBR * FLQ;

    const int tid = threadIdx.x;
    const int w = tid >> 5;
    const int warp_m = (w & 3) * 32;
    const int warp_n = (w >> 2) * 32;

    const long long qrow0 = (long long)(b * SEQ + m0);

    #pragma unroll
    for (int it = 0; it < 4; it++) {
        int v = tid + it * 256;
        int row = v >> 3, c8 = v & 7;
        long long g = (qrow0 + row) * QKVN + hc + c8 * 8;
        cp16(sQh + row * FLQ + c8 * 8, qkvh + g);
        cp16(sQl + row * FLQ + c8 * 8, qkvl + g);
    }
    cp_commit();

    auto load_kv = [&](int jt, int s) {
        const long long krow0 = (long long)(b * SEQ + jt * FBC);
        bf16* kH = sK + s * 2 * FBC * FLQ;
        bf16* kL = kH + FBC * FLQ;
        bf16* vH = sV + s * 2 * FBC * FLQ;
        bf16* vL = vH + FBC * FLQ;
        #pragma unroll
        for (int it = 0; it < 2; it++) {
            int v = tid + it * 256;
            int row = v >> 3, c8 = v & 7;
            long long gk = (krow0 + row) * QKVN + DDIM + hc + c8 * 8;
            long long gv = (krow0 + row) * QKVN + 2 * DDIM + hc + c8 * 8;
            cp16(kH + row * FLQ + c8 * 8, qkvh + gk);
            cp16(kL + row * FLQ + c8 * 8, qkvl + gk);
            cp16(vH + row * FLQ + c8 * 8, qkvh + gv);
            cp16(vL + row * FLQ + c8 * 8, qkvl + gv);
        }
    };

    const int nj = m0 / FBC + 2;
    load_kv(0, 0);
    cp_commit();

    const int row = tid >> 1;
    const int col0 = (tid & 1) * 32;
    float Oreg[32];
    #pragma unroll
    for (int c = 0; c < 32; c++) Oreg[c] = 0.f;
    float mrow = -1e30f, lrow = 0.f;

    for (int jt = 0; jt < nj; jt++) {
        const int s = jt & 1;
        if (jt + 1 < nj) { load_kv(jt + 1, s ^ 1); cp_commit(); cp_wait<1>(); }
        else             cp_wait<0>();
        __syncthreads();

        bf16* kH = sK + s * 2 * FBC * FLQ;
        bf16* kL = kH + FBC * FLQ;
        bf16* vH = sV + s * 2 * FBC * FLQ;
        bf16* vL = vH + FBC * FLQ;

        {
            wmma::fragment<wmma::accumulator, 16, 16, 16, float> sacc[2][2];
            #pragma unroll
            for (int i = 0; i < 2; i++)
                #pragma unroll
                for (int j = 0; j < 2; j++) wmma::fill_fragment(sacc[i][j], 0.f);
            #pragma unroll
            for (int kk = 0; kk < 4; kk++) {
                wmma::fragment<wmma::matrix_a, 16, 16, 16, bf16, wmma::row_major> ahi[2], alo[2];
                #pragma unroll
                for (int i = 0; i < 2; i++) {
                    int off = (warp_m + i * 16) * FLQ + kk * 16;
                    wmma::load_matrix_sync(ahi[i], sQh + off, FLQ);
                    wmma::load_matrix_sync(alo[i], sQl + off, FLQ);
                }
                #pragma unroll
                for (int j = 0; j < 2; j++) {
                    wmma::fragment<wmma::matrix_b, 16, 16, 16, bf16, wmma::col_major> bhi, blo;
                    int off = (warp_n + j * 16) * FLQ + kk * 16;
                    wmma::load_matrix_sync(bhi, kH + off, FLQ);
                    wmma::load_matrix_sync(blo, kL + off, FLQ);
                    #pragma unroll
                    for (int i = 0; i < 2; i++) {
                        wmma::mma_sync(sacc[i][j], ahi[i], bhi, sacc[i][j]);
                        wmma::mma_sync(sacc[i][j], ahi[i], blo, sacc[i][j]);
                        wmma::mma_sync(sacc[i][j], alo[i], bhi, sacc[i][j]);
                    }
                }
            }
            #pragma unroll
            for (int i = 0; i < 2; i++)
                #pragma unroll
                for (int j = 0; j < 2; j++)
                    wmma::store_matrix_sync(sS + (warp_m + i * 16) * FLS + warp_n + j * 16,
                                            sacc[i][j], FLS, wmma::mem_row_major);
        }
        __syncthreads();

        {
            const int jbase = jt * FBC;
            const int rlimit = m0 + row;
            float sv[32];
            float bmax = -1e30f;
            #pragma unroll
            for (int c = 0; c < 32; c++) {
                float vv = sS[row * FLS + col0 + c];
                if (jbase + col0 + c > rlimit) vv = -1e30f;
                sv[c] = vv;
                bmax = fmaxf(bmax, vv);
            }
            bmax = fmaxf(bmax, __shfl_xor_sync(0xffffffffu, bmax, 1));
            float m_new = fmaxf(mrow, bmax);
            float alpha = __expf(mrow - m_new);
            float psum = 0.f;
            #pragma unroll
            for (int c = 0; c < 32; c++) {
                float e = __expf(sv[c] - m_new);
                sv[c] = e;
                psum += e;
            }
            psum += __shfl_xor_sync(0xffffffffu, psum, 1);
            lrow = lrow * alpha + psum;
            mrow = m_new;
            #pragma unroll
            for (int c = 0; c < 32; c++) Oreg[c] *= alpha;
            #pragma unroll
            for (int c = 0; c < 32; c++) {
                bf16 hh, ll; split2(sv[c], hh, ll);
                sPh[row * FLQ + col0 + c] = hh;
                sPl[row * FLQ + col0 + c] = ll;
            }
        }
        __syncthreads();

        {
            wmma::fragment<wmma::accumulator, 16, 16, 16, float> pv[2][2];
            #pragma unroll
            for (int i = 0; i < 2; i++)
                #pragma unroll
                for (int j = 0; j < 2; j++) wmma::fill_fragment(pv[i][j], 0.f);
            #pragma unroll
            for (int kk = 0; kk < 4; kk++) {
                wmma::fragment<wmma::matrix_a, 16, 16, 16, bf16, wmma::row_major> phi[2], plo[2];
                #pragma unroll
                for (int i = 0; i < 2; i++) {
                    int off = (warp_m + i * 16) * FLQ + kk * 16;
                    wmma::load_matrix_sync(phi[i], sPh + off, FLQ);
                    wmma::load_matrix_sync(plo[i], sPl + off, FLQ);
                }
                #pragma unroll
                for (int j = 0; j < 2; j++) {
                    wmma::fragment<wmma::matrix_b, 16, 16, 16, bf16, wmma::row_major> vhi, vlo;
                    int off = (kk * 16) * FLQ + warp_n + j * 16;
                    wmma::load_matrix_sync(vhi, vH + off, FLQ);
                    wmma::load_matrix_sync(vlo, vL + off, FLQ);
                    #pragma unroll
                    for (int i = 0; i < 2; i++) {
                        wmma::mma_sync(pv[i][j], phi[i], vhi, pv[i][j]);
                        wmma::mma_sync(pv[i][j], phi[i], vlo, pv[i][j]);
                        wmma::mma_sync(pv[i][j], plo[i], vhi, pv[i][j]);
                    }
                }
            }
            __syncthreads();
            #pragma unroll
            for (int i = 0; i < 2; i++)
                #pragma unroll
                for (int j = 0; j < 2; j++)
                    wmma::store_matrix_sync(sS + (warp_m + i * 16) * FLS + warp_n + j * 16,
                                            pv[i][j], FLS, wmma::mem_row_major);
        }
        __syncthreads();

        #pragma unroll
        for (int c = 0; c < 32; c++) Oreg[c] += sS[row * FLS + col0 + c];
    }

    const float inv = 1.0f / lrow;
    const long long obase = (qrow0 + row) * DDIM + hc + col0;
    #pragma unroll
    for (int c = 0; c < 32; c++) {
        bf16 hh, ll; split2(Oreg[c] * inv, hh, ll);
        aoh[obase + c] = hh;
        aol[obase + c] = ll;
    }
}

// ---------------- bf16-split tensor-core GEMM, cp.async double-buffered ------------
// NW = warps/block. SWAPXY: m on blockIdx.x. PARTIAL: split-K, write raw partials
// to Cg + blockIdx.z*zstride, K range = [blockIdx.z*Kchunk, +Kchunk).
template<int BM, int BN, int BK, int WM, int WN, int NW,
         bool TRANSB, bool RELU, bool RESID, bool OSPLIT, bool SWAPXY, bool PARTIAL>
__global__ void __launch_bounds__(NW * 32, (NW == 8) ? 2 : 4) gemm_tc(
    const bf16* __restrict__ Ahig, const bf16* __restrict__ Alog,
    const bf16* __restrict__ Bhig, const bf16* __restrict__ Blog,
    const float* __restrict__ biasg,
    float* __restrict__ Cg, bf16* __restrict__ Chig, bf16* __restrict__ Clog,
    int Kchunk, int lda, int ldb, int ldc, long long zstride)
{
    constexpr int NT = NW * 32;
    constexpr int LDA = BK + 8;
    constexpr int BROWS = TRANSB ? BN : BK;
    constexpr int LDB = TRANSB ? (BK + 8) : (BN + 8);
    constexpr int A_EL = BM * LDA;
    constexpr int B_EL = BROWS * LDB;
    constexpr int MI = WM / 16, NI = WN / 16;
    static_assert((BM / WM) * (BN / WN) == NW, "warp layout");

    const int bxn = SWAPXY ? blockIdx.y : blockIdx.x;
    const int bym = SWAPXY ? blockIdx.x : blockIdx.y;
    const int m0 = bym * BM;
    const int n0 = bxn * BN;
    const int kbeg = PARTIAL ? (int)blockIdx.z * Kchunk : 0;

    extern __shared__ char smraw[];
    bf16* sAhi = (bf16*)smraw;
    bf16* sAlo = sAhi + 2 * A_EL;
    bf16* sBhi = sAlo + 2 * A_EL;
    bf16* sBlo = sBhi + 2 * B_EL;
    float* stg = (float*)smraw;    // aliases A buffers; used only after final sync

    const int tid = threadIdx.x;
    const int w = tid >> 5, lane = tid & 31;
    const int warp_m = (w / (BN / WN)) * WM;
    const int warp_n = (w % (BN / WN)) * WN;

    wmma::fragment<wmma::accumulator, 16, 16, 16, float> acc[MI][NI];
    #pragma unroll
    for (int i = 0; i < MI; i++)
        #pragma unroll
        for (int j = 0; j < NI; j++) wmma::fill_fragment(acc[i][j], 0.f);

    const int nk = Kchunk / BK;

    auto load_stage = [&](int kt, int s) {
        const int k0 = kbeg + kt * BK;
        constexpr int CA = BM * BK / 8;
        #pragma unroll
        for (int it = 0; it < CA / NT; it++) {
            int v = tid + it * NT;
            int row = v / (BK / 8), c = v % (BK / 8);
            long long g = (long long)(m0 + row) * lda + k0 + c * 8;
            int sm = s * A_EL + row * LDA + c * 8;
            cp16(sAhi + sm, Ahig + g);
            cp16(sAlo + sm, Alog + g);
        }
        constexpr int CB = BK * BN / 8;
        #pragma unroll
        for (int it = 0; it < CB / NT; it++) {
            int v = tid + it * NT;
            if (!TRANSB) {
                int row = v / (BN / 8), c = v % (BN / 8);
                long long g = (long long)(k0 + row) * ldb + n0 + c * 8;
                int sm = s * B_EL + row * LDB + c * 8;
                cp16(sBhi + sm, Bhig + g);
                cp16(sBlo + sm, Blog + g);
            } else {
                int row = v / (BK / 8), c = v % (BK / 8);
                long long g = (long long)(n0 + row) * ldb + k0 + c * 8;
                int sm = s * B_EL + row * LDB + c * 8;
                cp16(sBhi + sm, Bhig + g);
                cp16(sBlo + sm, Blog + g);
            }
        }
    };

    load_stage(0, 0);
    cp_commit();

    for (int kt = 0; kt < nk; kt++) {
        const int s = kt & 1;
        if (kt + 1 < nk) { load_stage(kt + 1, s ^ 1); cp_commit(); cp_wait<1>(); }
        else             cp_wait<0>();
        __syncthreads();

        #pragma unroll
        for (int kk = 0; kk < BK / 16; kk++) {
            wmma::fragment<wmma::matrix_a, 16, 16, 16, bf16, wmma::row_major> ahi[MI], alo[MI];
            #pragma unroll
            for (int i = 0; i < MI; i++) {
                int off = s * A_EL + (warp_m + i * 16) * LDA + kk * 16;
                wmma::load_matrix_sync(ahi[i], sAhi + off, LDA);
                wmma::load_matrix_sync(alo[i], sAlo + off, LDA);
            }
            #pragma unroll
            for (int j = 0; j < NI; j++) {
                if constexpr (TRANSB) {
                    wmma::fragment<wmma::matrix_b, 16, 16, 16, bf16, wmma::col_major> bhi, blo;
                    int off = s * B_EL + (warp_n + j * 16) * LDB + kk * 16;
                    wmma::load_matrix_sync(bhi, sBhi + off, LDB);
                    wmma::load_matrix_sync(blo, sBlo + off, LDB);
                    #pragma unroll
                    for (int i = 0; i < MI; i++) {
                        wmma::mma_sync(acc[i][j], ahi[i], bhi, acc[i][j]);
                        wmma::mma_sync(acc[i][j], ahi[i], blo, acc[i][j]);
                        wmma::mma_sync(acc[i][j], alo[i], bhi, acc[i][j]);
                    }
                } else {
                    wmma::fragment<wmma::matrix_b, 16, 16, 16, bf16, wmma::row_major> bhi, blo;
                    int off = s * B_EL + (kk * 16) * LDB + warp_n + j * 16;
                    wmma::load_matrix_sync(bhi, sBhi + off, LDB);
                    wmma::load_matrix_sync(blo, sBlo + off, LDB);
                    #pragma unroll
                    for (int i = 0; i < MI; i++) {
                        wmma::mma_sync(acc[i][j], ahi[i], bhi, acc[i][j]);
                        wmma::mma_sync(acc[i][j], ahi[i], blo, acc[i][j]);
                        wmma::mma_sync(acc[i][j], alo[i], bhi, acc[i][j]);
                    }
                }
            }
        }
        __syncthreads();
    }

    // ---- epilogue via per-warp smem staging (aliased onto A buffers) ----
    float* Cout = PARTIAL ? (Cg + (long long)blockIdx.z * zstride) : Cg;
    #pragma unroll
    for (int i = 0; i < MI; i++) {
        #pragma unroll
        for (int j = 0; j < NI; j++) {
            wmma::store_matrix_sync(stg + w * 256, acc[i][j], 16, wmma::mem_row_major);
            __syncwarp();
            #pragma unroll
            for (int e = 0; e < 8; e++) {
                int idx = lane + 32 * e;
                int r = idx >> 4, c = idx & 15;
                int m = m0 + warp_m + i * 16 + r;
                int n = n0 + warp_n + j * 16 + c;
                long long cidx = (long long)m * ldc + n;
                float v = stg[w * 256 + idx];
                if (PARTIAL) {
                    Cout[cidx] = v;
                } else {
                    if (biasg) v += __ldg(biasg + n);
                    if (RESID) v += Cg[cidx];
                    if (RELU)  v = fmaxf(v, 0.f);
                    if (OSPLIT) { bf16 h, l; split2(v, h, l); Chig[cidx] = h; Clog[cidx] = l; }
                    else        Cg[cidx] = v;
                }
            }
            __syncwarp();
        }
    }
}

// ---------------- host launchers ----------------
template<int BM, int BN, int BK, int WM, int WN, int NW,
         bool TRANSB, bool RELU, bool RESID, bool OSPLIT, bool SWAPXY = false>
static void run_gemm(const bf16* Ahi, const bf16* Alo, const bf16* Bhi, const bf16* Blo,
                     const float* bias, float* C, bf16* Chi, bf16* Clo,
                     int M, int N, int K, int lda, int ldb, int ldc)
{
    constexpr int LDA = BK + 8;
    constexpr int BROWS = TRANSB ? BN : BK;
    constexpr int LDB = TRANSB ? (BK + 8) : (BN + 8);
    constexpr size_t SB = (size_t)8 * BM * LDA + (size_t)8 * BROWS * LDB;
    auto fn = gemm_tc<BM, BN, BK, WM, WN, NW, TRANSB, RELU, RESID, OSPLIT, SWAPXY, false>;
    cudaFuncSetAttribute(fn, cudaFuncAttributeMaxDynamicSharedMemorySize, (int)SB);
    dim3 grid = SWAPXY ? dim3(M / BM, N / BN) : dim3(N / BN, M / BM);
    fn<<<grid, NW * 32, SB>>>(Ahi, Alo, Bhi, Blo, bias, C, Chi, Clo, K, lda, ldb, ldc, 0);
}

// split-K x2 -> raw partials into part (z-stride M*ldc)
template<int BM, int BN, int BK, int WM, int WN, int NW>
static void run_gemm_sk(const bf16* Ahi, const bf16* Alo, const bf16* Bhi, const bf16* Blo,
                        float* part, int M, int N, int K, int lda, int ldb, int ldc)
{
    constexpr int LDA = BK + 8;
    constexpr int LDB = BN + 8;
    constexpr size_t SB = (size_t)8 * BM * LDA + (size_t)8 * BK * LDB;
    auto fn = gemm_tc<BM, BN, BK, WM, WN, NW, false, false, false, false, false, true>;
    cudaFuncSetAttribute(fn, cudaFuncAttributeMaxDynamicSharedMemorySize, (int)SB);
    dim3 grid(N / BN, M / BM, 2);
    fn<<<grid, NW * 32, SB>>>(Ahi, Alo, Bhi, Blo, nullptr, part, nullptr, nullptr,
                              K / 2, lda, ldb, ldc, (long long)M * ldc);
}

extern "C" void kernel_launch(void* const* d_in, const int* in_sizes, int n_in,
                              void* d_out, int out_size)
{
    const int*   X      = (const int*)  d_in[0];
    const float* emb    = (const float*)d_in[1];
    const float* pos    = (const float*)d_in[2];
    const float* Wq     = (const float*)d_in[3];
    const float* bq     = (const float*)d_in[4];
    const float* Wk     = (const float*)d_in[5];
    const float* bk     = (const float*)d_in[6];
    const float* Wv     = (const float*)d_in[7];
    const float* bv     = (const float*)d_in[8];
    const float* Wo     = (const float*)d_in[9];
    const float* bo     = (const float*)d_in[10];
    const float* ln1s   = (const float*)d_in[11];
    const float* ln1b   = (const float*)d_in[12];
    const float* ln2s   = (const float*)d_in[13];
    const float* ln2b   = (const float*)d_in[14];
    const float* W1     = (const float*)d_in[15];
    const float* b1     = (const float*)d_in[16];
    const float* W2     = (const float*)d_in[17];
    const float* b2     = (const float*)d_in[18];
    const float* lnfs   = (const float*)d_in[19];
    const float* lnfb   = (const float*)d_in[20];
    const float* headb  = (const float*)d_in[21];
    float* out = (float*)d_out;

    float *x, *bqkv, *part;
    bf16 *xnh, *xnl, *qkvh, *qkvl, *aoh, *aol, *h1h, *h1l;
    bf16 *wqkvh, *wqkvl, *woh, *wol, *w1h, *w1l, *w2h, *w2l, *embh, *embl;
    cudaGetSymbolAddress((void**)&x,     g_x);
    cudaGetSymbolAddress((void**)&part,  g_part);
    cudaGetSymbolAddress((void**)&xnh,   g_xnh);
    cudaGetSymbolAddress((void**)&xnl,   g_xnl);
    cudaGetSymbolAddress((void**)&qkvh,  g_qkvh);
    cudaGetSymbolAddress((void**)&qkvl,  g_qkvl);
    cudaGetSymbolAddress((void**)&aoh,   g_aoh);
    cudaGetSymbolAddress((void**)&aol,   g_aol);
    cudaGetSymbolAddress((void**)&h1h,   g_h1h);
    cudaGetSymbolAddress((void**)&h1l,   g_h1l);
    cudaGetSymbolAddress((void**)&wqkvh, g_wqkvh);
    cudaGetSymbolAddress((void**)&wqkvl, g_wqkvl);
    cudaGetSymbolAddress((void**)&bqkv,  g_bqkv);
    cudaGetSymbolAddress((void**)&woh,   g_woh);
    cudaGetSymbolAddress((void**)&wol,   g_wol);
    cudaGetSymbolAddress((void**)&w1h,   g_w1h);
    cudaGetSymbolAddress((void**)&w1l,   g_w1l);
    cudaGetSymbolAddress((void**)&w2h,   g_w2h);
    cudaGetSymbolAddress((void**)&w2l,   g_w2l);
    cudaGetSymbolAddress((void**)&embh,  g_embh);
    cudaGetSymbolAddress((void**)&embl,  g_embl);

    // ---- weight pre-split (once per call) ----
    split_qkv_k<<<13824, 256>>>(Wq, wqkvh, wqkvl, 0,        0.125f);  // fold 1/sqrt(64)
    split_qkv_k<<<13824, 256>>>(Wk, wqkvh, wqkvl, DDIM,     1.0f);
    split_qkv_k<<<13824, 256>>>(Wv, wqkvh, wqkvl, 2 * DDIM, 1.0f);
    bias_qkv_k<<<54, 256>>>(bq, bk, bv);
    split_plain_k<<< 3456, 256>>>((const float4*)Wo,  woh,  wol,  (long long)LNUM*DDIM*DDIM/4);
    split_plain_k<<<13824, 256>>>((const float4*)W1,  w1h,  w1l,  (long long)LNUM*DDIM*FDIM/4);
    split_plain_k<<<13824, 256>>>((const float4*)W2,  w2h,  w2l,  (long long)LNUM*FDIM*DDIM/4);
    split_plain_k<<<24000, 256>>>((const float4*)emb, embh, embl, (long long)VOC*DDIM/4);

    // x = emb[X] + pos
    embed_k<<<TTOK, 256>>>(X, emb, pos, x);

    // flash smem (R9 layout)
    const int FSMEM = (2 * FBR * FLQ + 2 * 2 * 2 * FBC * FLQ + 2 * FBR * FLQ) * 2
                      + FBR * FLS * 4;
    cudaFuncSetAttribute(flash_k, cudaFuncAttributeMaxDynamicSharedMemorySize, FSMEM);

    const long long zD = (long long)TTOK * DDIM;   // partial z-stride for N=768
    const long long zF = (long long)TTOK * FDIM;   // for N=3072

    for (int l = 0; l < LNUM; l++) {
        // xn = LN1(x) (split)
        ln_k<<<TTOK, 256>>>(x, ln1s + l * DDIM, ln1b + l * DDIM, xnh, xnl);

        // fused qkv = xn @ Wqkv + bqkv -> split [T, 2304]  (128x128, 8 warps)
        run_gemm<128, 128, 32, 32, 64, 8, false, false, false, true>(
            xnh, xnl, wqkvh + (long long)l * DDIM * QKVN, wqkvl + (long long)l * DDIM * QKVN,
            bqkv + l * QKVN, nullptr, qkvh, qkvl,
            TTOK, QKVN, DDIM, DDIM, QKVN, QKVN);

        // fused causal attention -> ao (split)
        {
            dim3 fg(BAT * HNUM, SEQ / FBR);
            flash_k<<<fg, 256, FSMEM>>>(qkvh, qkvl, aoh, aol);
        }

        // x += ao @ Wo + bo   (split-K x2: 64x64 tiles, 768 blocks)
        run_gemm_sk<64, 64, 32, 32, 32, 4>(
            aoh, aol, woh + (long long)l * DDIM * DDIM, wol + (long long)l * DDIM * DDIM,
            part, TTOK, DDIM, DDIM, DDIM, DDIM, DDIM);
        reduce_resid_k<<<TTOK * DDIM / 4 / 256, 256>>>(part, x, bo + l * DDIM, DDIM, zD);

        // xn = LN2(x)
        ln_k<<<TTOK, 256>>>(x, ln2s + l * DDIM, ln2b + l * DDIM, xnh, xnl);

        // h1 = relu(xn @ W1 + b1) -> split   (split-K x2: 128x128, 768 blocks)
        run_gemm_sk<128, 128, 32, 32, 64, 8>(
            xnh, xnl, w1h + (long long)l * DDIM * FDIM, w1l + (long long)l * DDIM * FDIM,
            part, TTOK, FDIM, DDIM, DDIM, FDIM, FDIM);
        reduce_relu_split_k<<<TTOK * FDIM / 4 / 256, 256>>>(part, h1h, h1l,
                                                            b1 + l * FDIM, FDIM, zF);

        // x += h1 @ W2 + b2   (split-K x2: 64x64 tiles, 768 blocks @ K=1536)
        run_gemm_sk<64, 64, 32, 32, 32, 4>(
            h1h, h1l, w2h + (long long)l * FDIM * DDIM, w2l + (long long)l * FDIM * DDIM,
            part, TTOK, DDIM, FDIM, FDIM, DDIM, DDIM);
        reduce_resid_k<<<TTOK * DDIM / 4 / 256, 256>>>(part, x, b2 + l * DDIM, DDIM, zD);
    }

    // xn = LNf(x)
    ln_k<<<TTOK, 256>>>(x, lnfs, lnfb, xnh, xnl);

    // logits = xn @ emb^T + head_b  (128x128, 8 warps, SWAPXY: m fast, B L2 reuse)
    run_gemm<128, 128, 32, 32, 64, 8, true, false, false, false, true>(
        xnh, xnl, embh, embl, headb, out, nullptr, nullptr,
        TTOK, VOC, DDIM, DDIM, DDIM, VOC);
}

// round 13
// speedup vs baseline: 1.5654x; 1.5654x over previous
#include <cuda_runtime.h>
#include <cuda_bf16.h>
#include <mma.h>
#include <cstdint>

using namespace nvcuda;
typedef __nv_bfloat16 bf16;

#define LNUM 6
#define HNUM 12
#define DDIM 768
#define DHD  64
#define FDIM 3072
#define VOC  32000
#define SEQ  1024
#define BAT  2
#define TTOK (BAT*SEQ)
#define QKVN (3*DDIM)
#define EPS  1e-5f

// ---------------- scratch (static device globals; no allocation) ----------------
__device__ float g_x [TTOK*DDIM];
__device__ bf16 g_xnh[TTOK*DDIM],  g_xnl[TTOK*DDIM];
__device__ bf16 g_qkvh[(long long)TTOK*QKVN], g_qkvl[(long long)TTOK*QKVN];
__device__ bf16 g_aoh[TTOK*DDIM],  g_aol[TTOK*DDIM];
__device__ bf16 g_h1h[(long long)TTOK*FDIM], g_h1l[(long long)TTOK*FDIM];
// pre-split weights
__device__ bf16 g_wqkvh[(long long)LNUM*DDIM*QKVN], g_wqkvl[(long long)LNUM*DDIM*QKVN];
__device__ float g_bqkv[LNUM*QKVN];
__device__ bf16 g_woh[(long long)LNUM*DDIM*DDIM],  g_wol[(long long)LNUM*DDIM*DDIM];
__device__ bf16 g_w1h[(long long)LNUM*DDIM*FDIM],  g_w1l[(long long)LNUM*DDIM*FDIM];
__device__ bf16 g_w2h[(long long)LNUM*FDIM*DDIM],  g_w2l[(long long)LNUM*FDIM*DDIM];
__device__ bf16 g_embh[(long long)VOC*DDIM],       g_embl[(long long)VOC*DDIM];

// ---------------- helpers ----------------
__device__ __forceinline__ void split2(float v, bf16& h, bf16& l) {
    h = __float2bfloat16(v);
    l = __float2bfloat16(v - __bfloat162float(h));
}
__device__ __forceinline__ void cp16(bf16* dst, const bf16* src) {
    unsigned int d = (unsigned int)__cvta_generic_to_shared(dst);
    asm volatile("cp.async.cg.shared.global [%0], [%1], 16;" :: "r"(d), "l"(src));
}
__device__ __forceinline__ void cp_commit() { asm volatile("cp.async.commit_group;"); }
template<int N> __device__ __forceinline__ void cp_wait() {
    asm volatile("cp.async.wait_group %0;" :: "n"(N));
}
__device__ __forceinline__ float warp_sum(float v) {
    #pragma unroll
    for (int o = 16; o; o >>= 1) v += __shfl_xor_sync(0xffffffffu, v, o);
    return v;
}

// ---------------- weight pre-split kernels ----------------
__global__ void split_qkv_k(const float* __restrict__ src, bf16* __restrict__ hi,
                            bf16* __restrict__ lo, int coloff, float scale)
{
    long long idx = (long long)blockIdx.x * 256 + threadIdx.x;
    int kk = (int)(idx & (DHD - 1));
    long long t = idx >> 6;
    int d = (int)(t % DDIM); t /= DDIM;
    int h = (int)(t % HNUM);
    int l = (int)(t / HNUM);
    long long dst = ((long long)l * DDIM + d) * QKVN + coloff + h * DHD + kk;
    float v = src[idx] * scale;
    bf16 hh, ll; split2(v, hh, ll);
    hi[dst] = hh; lo[dst] = ll;
}

__global__ void bias_qkv_k(const float* __restrict__ bq, const float* __restrict__ bk,
                           const float* __restrict__ bv)
{
    int i = blockIdx.x * 256 + threadIdx.x;
    int col = i % QKVN, l = i / QKVN;
    float v;
    if (col < DDIM)            v = bq[l * DDIM + col] * 0.125f;
    else if (col < 2 * DDIM)   v = bk[l * DDIM + col - DDIM];
    else                       v = bv[l * DDIM + col - 2 * DDIM];
    g_bqkv[i] = v;
}

__global__ void split_plain_k(const float4* __restrict__ src, bf16* __restrict__ hi,
                              bf16* __restrict__ lo, long long n4)
{
    long long i = (long long)blockIdx.x * 256 + threadIdx.x;
    if (i >= n4) return;
    float4 v = src[i];
    bf16 h, l;
    __nv_bfloat162* h2 = (__nv_bfloat162*)hi;
    __nv_bfloat162* l2 = (__nv_bfloat162*)lo;
    __nv_bfloat162 ha, hb, la, lb;
    split2(v.x, h, l); ha.x = h; la.x = l;
    split2(v.y, h, l); ha.y = h; la.y = l;
    split2(v.z, h, l); hb.x = h; lb.x = l;
    split2(v.w, h, l); hb.y = h; lb.y = l;
    h2[2*i] = ha; h2[2*i+1] = hb;
    l2[2*i] = la; l2[2*i+1] = lb;
}

// ---------------- embedding ----------------
__global__ void embed_k(const int* __restrict__ X, const float* __restrict__ emb,
                        const float* __restrict__ pos, float* __restrict__ x)
{
    int t = blockIdx.x;
    int tok = X[t];
    int s = t % SEQ;
    const float* er = emb + (long long)tok * DDIM;
    const float* pr = pos + (long long)s * DDIM;
    float* xr = x + (long long)t * DDIM;
    for (int d = threadIdx.x; d < DDIM; d += blockDim.x)
        xr[d] = er[d] + pr[d];
}

// ---------------- layernorm -> split bf16 output (vectorized, reg-cached) --------
__global__ void ln_k(const float* __restrict__ x, const float* __restrict__ g,
                     const float* __restrict__ b, bf16* __restrict__ yh,
                     bf16* __restrict__ yl)
{
    int row = blockIdx.x;
    const float4* xr = (const float4*)(x + (long long)row * DDIM);   // 192 float4
    __nv_bfloat162* yhr = (__nv_bfloat162*)(yh + (long long)row * DDIM);
    __nv_bfloat162* ylr = (__nv_bfloat162*)(yl + (long long)row * DDIM);
    int tid = threadIdx.x;   // 0..191 active for loads (192 float4); 256 threads

    float4 v[1];
    float lv[4] = {0.f, 0.f, 0.f, 0.f};
    bool act = tid < 192;
    if (act) {
        v[0] = xr[tid];
        lv[0] = v[0].x; lv[1] = v[0].y; lv[2] = v[0].z; lv[3] = v[0].w;
    }
    float sum = lv[0] + lv[1] + lv[2] + lv[3];
    float sq  = lv[0]*lv[0] + lv[1]*lv[1] + lv[2]*lv[2] + lv[3]*lv[3];

    __shared__ float shs[8], shq[8];
    float s1 = warp_sum(sum), s2 = warp_sum(sq);
    int wid = tid >> 5, lane = tid & 31;
    if (lane == 0) { shs[wid] = s1; shq[wid] = s2; }
    __syncthreads();
    float ts = 0.f, tq = 0.f;
    #pragma unroll
    for (int w = 0; w < 8; w++) { ts += shs[w]; tq += shq[w]; }
    float mu = ts * (1.0f / DDIM);
    float var = tq * (1.0f / DDIM) - mu * mu;
    float r = rsqrtf(var + EPS);

    if (act) {
        const float4 gv = ((const float4*)g)[tid];
        const float4 bv = ((const float4*)b)[tid];
        float o0 = (lv[0] - mu) * r * gv.x + bv.x;
        float o1 = (lv[1] - mu) * r * gv.y + bv.y;
        float o2 = (lv[2] - mu) * r * gv.z + bv.z;
        float o3 = (lv[3] - mu) * r * gv.w + bv.w;
        bf16 h, l;
        __nv_bfloat162 ha, hb, la, lb;
        split2(o0, h, l); ha.x = h; la.x = l;
        split2(o1, h, l); ha.y = h; la.y = l;
        split2(o2, h, l); hb.x = h; lb.x = l;
        split2(o3, h, l); hb.y = h; lb.y = l;
        yhr[2*tid] = ha; yhr[2*tid+1] = hb;
        ylr[2*tid] = la; ylr[2*tid+1] = lb;
    }
}

// ---------------- fused causal flash attention (R9 version) ----------------
#define FBR 128
#define FBC 64
#define FLQ 72
#define FLS 68
__global__ void __launch_bounds__(256, 1) flash_k(
    const bf16* __restrict__ qkvh, const bf16* __restrict__ qkvl,
    bf16* __restrict__ aoh, bf16* __restrict__ aol)
{
    const int bh = blockIdx.x;
    const int b = bh / HNUM, h = bh - b * HNUM;
    const int m0 = (gridDim.y - 1 - blockIdx.y) * FBR;
    const int hc = h * DHD;

    extern __shared__ char smraw[];
    bf16* sQh = (bf16*)smraw;
    bf16* sQl = sQh + FBR * FLQ;
    bf16* sK  = sQl + FBR * FLQ;
    bf16* sV  = sK + 2 * 2 * FBC * FLQ;
    float* sS = (float*)(sV + 2 * 2 * FBC * FLQ);
    bf16* sPh = (bf16*)(sS + FBR * FLS);
    bf16* sPl = sPh + FBR * FLQ;

    const int tid = threadIdx.x;
    const int w = tid >> 5;
    const int warp_m = (w & 3) * 32;
    const int warp_n = (w >> 2) * 32;

    const long long qrow0 = (long long)(b * SEQ + m0);

    #pragma unroll
    for (int it = 0; it < 4; it++) {
        int v = tid + it * 256;
        int row = v >> 3, c8 = v & 7;
        long long g = (qrow0 + row) * QKVN + hc + c8 * 8;
        cp16(sQh + row * FLQ + c8 * 8, qkvh + g);
        cp16(sQl + row * FLQ + c8 * 8, qkvl + g);
    }
    cp_commit();

    auto load_kv = [&](int jt, int s) {
        const long long krow0 = (long long)(b * SEQ + jt * FBC);
        bf16* kH = sK + s * 2 * FBC * FLQ;
        bf16* kL = kH + FBC * FLQ;
        bf16* vH = sV + s * 2 * FBC * FLQ;
        bf16* vL = vH + FBC * FLQ;
        #pragma unroll
        for (int it = 0; it < 2; it++) {
            int v = tid + it * 256;
            int row = v >> 3, c8 = v & 7;
            long long gk = (krow0 + row) * QKVN + DDIM + hc + c8 * 8;
            long long gv = (krow0 + row) * QKVN + 2 * DDIM + hc + c8 * 8;
            cp16(kH + row * FLQ + c8 * 8, qkvh + gk);
            cp16(kL + row * FLQ + c8 * 8, qkvl + gk);
            cp16(vH + row * FLQ + c8 * 8, qkvh + gv);
            cp16(vL + row * FLQ + c8 * 8, qkvl + gv);
        }
    };

    const int nj = m0 / FBC + 2;
    load_kv(0, 0);
    cp_commit();

    const int row = tid >> 1;
    const int col0 = (tid & 1) * 32;
    float Oreg[32];
    #pragma unroll
    for (int c = 0; c < 32; c++) Oreg[c] = 0.f;
    float mrow = -1e30f, lrow = 0.f;

    for (int jt = 0; jt < nj; jt++) {
        const int s = jt & 1;
        if (jt + 1 < nj) { load_kv(jt + 1, s ^ 1); cp_commit(); cp_wait<1>(); }
        else             cp_wait<0>();
        __syncthreads();

        bf16* kH = sK + s * 2 * FBC * FLQ;
        bf16* kL = kH + FBC * FLQ;
        bf16* vH = sV + s * 2 * FBC * FLQ;
        bf16* vL = vH + FBC * FLQ;

        {
            wmma::fragment<wmma::accumulator, 16, 16, 16, float> sacc[2][2];
            #pragma unroll
            for (int i = 0; i < 2; i++)
                #pragma unroll
                for (int j = 0; j < 2; j++) wmma::fill_fragment(sacc[i][j], 0.f);
            #pragma unroll
            for (int kk = 0; kk < 4; kk++) {
                wmma::fragment<wmma::matrix_a, 16, 16, 16, bf16, wmma::row_major> ahi[2], alo[2];
                #pragma unroll
                for (int i = 0; i < 2; i++) {
                    int off = (warp_m + i * 16) * FLQ + kk * 16;
                    wmma::load_matrix_sync(ahi[i], sQh + off, FLQ);
                    wmma::load_matrix_sync(alo[i], sQl + off, FLQ);
                }
                #pragma unroll
                for (int j = 0; j < 2; j++) {
                    wmma::fragment<wmma::matrix_b, 16, 16, 16, bf16, wmma::col_major> bhi, blo;
                    int off = (warp_n + j * 16) * FLQ + kk * 16;
                    wmma::load_matrix_sync(bhi, kH + off, FLQ);
                    wmma::load_matrix_sync(blo, kL + off, FLQ);
                    #pragma unroll
                    for (int i = 0; i < 2; i++) {
                        wmma::mma_sync(sacc[i][j], ahi[i], bhi, sacc[i][j]);
                        wmma::mma_sync(sacc[i][j], ahi[i], blo, sacc[i][j]);
                        wmma::mma_sync(sacc[i][j], alo[i], bhi, sacc[i][j]);
                    }
                }
            }
            #pragma unroll
            for (int i = 0; i < 2; i++)
                #pragma unroll
                for (int j = 0; j < 2; j++)
                    wmma::store_matrix_sync(sS + (warp_m + i * 16) * FLS + warp_n + j * 16,
                                            sacc[i][j], FLS, wmma::mem_row_major);
        }
        __syncthreads();

        {
            const int jbase = jt * FBC;
            const int rlimit = m0 + row;
            float sv[32];
            float bmax = -1e30f;
            #pragma unroll
            for (int c = 0; c < 32; c++) {
                float vv = sS[row * FLS + col0 + c];
                if (jbase + col0 + c > rlimit) vv = -1e30f;
                sv[c] = vv;
                bmax = fmaxf(bmax, vv);
            }
            bmax = fmaxf(bmax, __shfl_xor_sync(0xffffffffu, bmax, 1));
            float m_new = fmaxf(mrow, bmax);
            float alpha = __expf(mrow - m_new);
            float psum = 0.f;
            #pragma unroll
            for (int c = 0; c < 32; c++) {
                float e = __expf(sv[c] - m_new);
                sv[c] = e;
                psum += e;
            }
            psum += __shfl_xor_sync(0xffffffffu, psum, 1);
            lrow = lrow * alpha + psum;
            mrow = m_new;
            #pragma unroll
            for (int c = 0; c < 32; c++) Oreg[c] *= alpha;
            #pragma unroll
            for (int c = 0; c < 32; c++) {
                bf16 hh, ll; split2(sv[c], hh, ll);
                sPh[row * FLQ + col0 + c] = hh;
                sPl[row * FLQ + col0 + c] = ll;
            }
        }
        __syncthreads();

        {
            wmma::fragment<wmma::accumulator, 16, 16, 16, float> pv[2][2];
            #pragma unroll
            for (int i = 0; i < 2; i++)
                #pragma unroll
                for (int j = 0; j < 2; j++) wmma::fill_fragment(pv[i][j], 0.f);
            #pragma unroll
            for (int kk = 0; kk < 4; kk++) {
                wmma::fragment<wmma::matrix_a, 16, 16, 16, bf16, wmma::row_major> phi[2], plo[2];
                #pragma unroll
                for (int i = 0; i < 2; i++) {
                    int off = (warp_m + i * 16) * FLQ + kk * 16;
                    wmma::load_matrix_sync(phi[i], sPh + off, FLQ);
                    wmma::load_matrix_sync(plo[i], sPl + off, FLQ);
                }
                #pragma unroll
                for (int j = 0; j < 2; j++) {
                    wmma::fragment<wmma::matrix_b, 16, 16, 16, bf16, wmma::row_major> vhi, vlo;
                    int off = (kk * 16) * FLQ + warp_n + j * 16;
                    wmma::load_matrix_sync(vhi, vH + off, FLQ);
                    wmma::load_matrix_sync(vlo, vL + off, FLQ);
                    #pragma unroll
                    for (int i = 0; i < 2; i++) {
                        wmma::mma_sync(pv[i][j], phi[i], vhi, pv[i][j]);
                        wmma::mma_sync(pv[i][j], phi[i], vlo, pv[i][j]);
                        wmma::mma_sync(pv[i][j], plo[i], vhi, pv[i][j]);
                    }
                }
            }
            __syncthreads();
            #pragma unroll
            for (int i = 0; i < 2; i++)
                #pragma unroll
                for (int j = 0; j < 2; j++)
                    wmma::store_matrix_sync(sS + (warp_m + i * 16) * FLS + warp_n + j * 16,
                                            pv[i][j], FLS, wmma::mem_row_major);
        }
        __syncthreads();

        #pragma unroll
        for (int c = 0; c < 32; c++) Oreg[c] += sS[row * FLS + col0 + c];
    }

    const float inv = 1.0f / lrow;
    const long long obase = (qrow0 + row) * DDIM + hc + col0;
    #pragma unroll
    for (int c = 0; c < 32; c++) {
        bf16 hh, ll; split2(Oreg[c] * inv, hh, ll);
        aoh[obase + c] = hh;
        aol[obase + c] = ll;
    }
}

// ---------------- bf16-split tensor-core GEMM, cp.async double-buffered ------------
// NW = warps/block (4 or 8). SWAPXY: read m from blockIdx.x (L2 reuse of B).
template<int BM, int BN, int BK, int WM, int WN, int NW,
         bool TRANSB, bool RELU, bool RESID, bool OSPLIT, bool SWAPXY>
__global__ void __launch_bounds__(NW * 32, (NW == 8) ? 2 : 4) gemm_tc(
    const bf16* __restrict__ Ahig, const bf16* __restrict__ Alog,
    const bf16* __restrict__ Bhig, const bf16* __restrict__ Blog,
    const float* __restrict__ biasg,
    float* __restrict__ Cg, bf16* __restrict__ Chig, bf16* __restrict__ Clog,
    int K, int lda, int ldb, int ldc)
{
    constexpr int NT = NW * 32;
    constexpr int LDA = BK + 8;
    constexpr int BROWS = TRANSB ? BN : BK;
    constexpr int LDB = TRANSB ? (BK + 8) : (BN + 8);
    constexpr int A_EL = BM * LDA;
    constexpr int B_EL = BROWS * LDB;
    constexpr int MI = WM / 16, NI = WN / 16;
    static_assert((BM / WM) * (BN / WN) == NW, "warp layout");

    const int bxn = SWAPXY ? blockIdx.y : blockIdx.x;
    const int bym = SWAPXY ? blockIdx.x : blockIdx.y;
    const int m0 = bym * BM;
    const int n0 = bxn * BN;

    extern __shared__ char smraw[];
    bf16* sAhi = (bf16*)smraw;
    bf16* sAlo = sAhi + 2 * A_EL;
    bf16* sBhi = sAlo + 2 * A_EL;
    bf16* sBlo = sBhi + 2 * B_EL;
    float* stg = (float*)smraw;    // aliases A buffers; used only after final sync

    const int tid = threadIdx.x;
    const int w = tid >> 5, lane = tid & 31;
    const int warp_m = (w / (BN / WN)) * WM;
    const int warp_n = (w % (BN / WN)) * WN;

    wmma::fragment<wmma::accumulator, 16, 16, 16, float> acc[MI][NI];
    #pragma unroll
    for (int i = 0; i < MI; i++)
        #pragma unroll
        for (int j = 0; j < NI; j++) wmma::fill_fragment(acc[i][j], 0.f);

    const int nk = K / BK;

    auto load_stage = [&](int kt, int s) {
        const int k0 = kt * BK;
        constexpr int CA = BM * BK / 8;
        #pragma unroll
        for (int it = 0; it < CA / NT; it++) {
            int v = tid + it * NT;
            int row = v / (BK / 8), c = v % (BK / 8);
            long long g = (long long)(m0 + row) * lda + k0 + c * 8;
            int sm = s * A_EL + row * LDA + c * 8;
            cp16(sAhi + sm, Ahig + g);
            cp16(sAlo + sm, Alog + g);
        }
        constexpr int CB = BK * BN / 8;
        #pragma unroll
        for (int it = 0; it < CB / NT; it++) {
            int v = tid + it * NT;
            if (!TRANSB) {
                int row = v / (BN / 8), c = v % (BN / 8);
                long long g = (long long)(k0 + row) * ldb + n0 + c * 8;
                int sm = s * B_EL + row * LDB + c * 8;
                cp16(sBhi + sm, Bhig + g);
                cp16(sBlo + sm, Blog + g);
            } else {
                int row = v / (BK / 8), c = v % (BK / 8);
                long long g = (long long)(n0 + row) * ldb + k0 + c * 8;
                int sm = s * B_EL + row * LDB + c * 8;
                cp16(sBhi + sm, Bhig + g);
                cp16(sBlo + sm, Blog + g);
            }
        }
    };

    load_stage(0, 0);
    cp_commit();

    for (int kt = 0; kt < nk; kt++) {
        const int s = kt & 1;
        if (kt + 1 < nk) { load_stage(kt + 1, s ^ 1); cp_commit(); cp_wait<1>(); }
        else             cp_wait<0>();
        __syncthreads();

        #pragma unroll
        for (int kk = 0; kk < BK / 16; kk++) {
            wmma::fragment<wmma::matrix_a, 16, 16, 16, bf16, wmma::row_major> ahi[MI], alo[MI];
            #pragma unroll
            for (int i = 0; i < MI; i++) {
                int off = s * A_EL + (warp_m + i * 16) * LDA + kk * 16;
                wmma::load_matrix_sync(ahi[i], sAhi + off, LDA);
                wmma::load_matrix_sync(alo[i], sAlo + off, LDA);
            }
            #pragma unroll
            for (int j = 0; j < NI; j++) {
                if constexpr (TRANSB) {
                    wmma::fragment<wmma::matrix_b, 16, 16, 16, bf16, wmma::col_major> bhi, blo;
                    int off = s * B_EL + (warp_n + j * 16) * LDB + kk * 16;
                    wmma::load_matrix_sync(bhi, sBhi + off, LDB);
                    wmma::load_matrix_sync(blo, sBlo + off, LDB);
                    #pragma unroll
                    for (int i = 0; i < MI; i++) {
                        wmma::mma_sync(acc[i][j], ahi[i], bhi, acc[i][j]);
                        wmma::mma_sync(acc[i][j], ahi[i], blo, acc[i][j]);
                        wmma::mma_sync(acc[i][j], alo[i], bhi, acc[i][j]);
                    }
                } else {
                    wmma::fragment<wmma::matrix_b, 16, 16, 16, bf16, wmma::row_major> bhi, blo;
                    int off = s * B_EL + (kk * 16) * LDB + warp_n + j * 16;
                    wmma::load_matrix_sync(bhi, sBhi + off, LDB);
                    wmma::load_matrix_sync(blo, sBlo + off, LDB);
                    #pragma unroll
                    for (int i = 0; i < MI; i++) {
                        wmma::mma_sync(acc[i][j], ahi[i], bhi, acc[i][j]);
                        wmma::mma_sync(acc[i][j], ahi[i], blo, acc[i][j]);
                        wmma::mma_sync(acc[i][j], alo[i], bhi, acc[i][j]);
                    }
                }
            }
        }
        __syncthreads();
    }

    // ---- epilogue via per-warp smem staging (aliased onto A buffers) ----
    #pragma unroll
    for (int i = 0; i < MI; i++) {
        #pragma unroll
        for (int j = 0; j < NI; j++) {
            wmma::store_matrix_sync(stg + w * 256, acc[i][j], 16, wmma::mem_row_major);
            __syncwarp();
            #pragma unroll
            for (int e = 0; e < 8; e++) {
                int idx = lane + 32 * e;
                int r = idx >> 4, c = idx & 15;
                int m = m0 + warp_m + i * 16 + r;
                int n = n0 + warp_n + j * 16 + c;
                long long cidx = (long long)m * ldc + n;
                float v = stg[w * 256 + idx];
                if (biasg) v += __ldg(biasg + n);
                if (RESID) v += Cg[cidx];
                if (RELU)  v = fmaxf(v, 0.f);
                if (OSPLIT) { bf16 h, l; split2(v, h, l); Chig[cidx] = h; Clog[cidx] = l; }
                else        Cg[cidx] = v;
            }
            __syncwarp();
        }
    }
}

// ---------------- host launcher ----------------
template<int BM, int BN, int BK, int WM, int WN, int NW,
         bool TRANSB, bool RELU, bool RESID, bool OSPLIT, bool SWAPXY = false>
static void run_gemm(const bf16* Ahi, const bf16* Alo, const bf16* Bhi, const bf16* Blo,
                     const float* bias, float* C, bf16* Chi, bf16* Clo,
                     int M, int N, int K, int lda, int ldb, int ldc)
{
    constexpr int LDA = BK + 8;
    constexpr int BROWS = TRANSB ? BN : BK;
    constexpr int LDB = TRANSB ? (BK + 8) : (BN + 8);
    constexpr size_t SB = (size_t)8 * BM * LDA + (size_t)8 * BROWS * LDB;
    auto fn = gemm_tc<BM, BN, BK, WM, WN, NW, TRANSB, RELU, RESID, OSPLIT, SWAPXY>;
    cudaFuncSetAttribute(fn, cudaFuncAttributeMaxDynamicSharedMemorySize, (int)SB);
    dim3 grid = SWAPXY ? dim3(M / BM, N / BN) : dim3(N / BN, M / BM);
    fn<<<grid, NW * 32, SB>>>(Ahi, Alo, Bhi, Blo, bias, C, Chi, Clo, K, lda, ldb, ldc);
}

extern "C" void kernel_launch(void* const* d_in, const int* in_sizes, int n_in,
                              void* d_out, int out_size)
{
    const int*   X      = (const int*)  d_in[0];
    const float* emb    = (const float*)d_in[1];
    const float* pos    = (const float*)d_in[2];
    const float* Wq     = (const float*)d_in[3];
    const float* bq     = (const float*)d_in[4];
    const float* Wk     = (const float*)d_in[5];
    const float* bk     = (const float*)d_in[6];
    const float* Wv     = (const float*)d_in[7];
    const float* bv     = (const float*)d_in[8];
    const float* Wo     = (const float*)d_in[9];
    const float* bo     = (const float*)d_in[10];
    const float* ln1s   = (const float*)d_in[11];
    const float* ln1b   = (const float*)d_in[12];
    const float* ln2s   = (const float*)d_in[13];
    const float* ln2b   = (const float*)d_in[14];
    const float* W1     = (const float*)d_in[15];
    const float* b1     = (const float*)d_in[16];
    const float* W2     = (const float*)d_in[17];
    const float* b2     = (const float*)d_in[18];
    const float* lnfs   = (const float*)d_in[19];
    const float* lnfb   = (const float*)d_in[20];
    const float* headb  = (const float*)d_in[21];
    float* out = (float*)d_out;

    float *x, *bqkv;
    bf16 *xnh, *xnl, *qkvh, *qkvl, *aoh, *aol, *h1h, *h1l;
    bf16 *wqkvh, *wqkvl, *woh, *wol, *w1h, *w1l, *w2h, *w2l, *embh, *embl;
    cudaGetSymbolAddress((void**)&x,     g_x);
    cudaGetSymbolAddress((void**)&xnh,   g_xnh);
    cudaGetSymbolAddress((void**)&xnl,   g_xnl);
    cudaGetSymbolAddress((void**)&qkvh,  g_qkvh);
    cudaGetSymbolAddress((void**)&qkvl,  g_qkvl);
    cudaGetSymbolAddress((void**)&aoh,   g_aoh);
    cudaGetSymbolAddress((void**)&aol,   g_aol);
    cudaGetSymbolAddress((void**)&h1h,   g_h1h);
    cudaGetSymbolAddress((void**)&h1l,   g_h1l);
    cudaGetSymbolAddress((void**)&wqkvh, g_wqkvh);
    cudaGetSymbolAddress((void**)&wqkvl, g_wqkvl);
    cudaGetSymbolAddress((void**)&bqkv,  g_bqkv);
    cudaGetSymbolAddress((void**)&woh,   g_woh);
    cudaGetSymbolAddress((void**)&wol,   g_wol);
    cudaGetSymbolAddress((void**)&w1h,   g_w1h);
    cudaGetSymbolAddress((void**)&w1l,   g_w1l);
    cudaGetSymbolAddress((void**)&w2h,   g_w2h);
    cudaGetSymbolAddress((void**)&w2l,   g_w2l);
    cudaGetSymbolAddress((void**)&embh,  g_embh);
    cudaGetSymbolAddress((void**)&embl,  g_embl);

    // ---- weight pre-split (once per call) ----
    split_qkv_k<<<13824, 256>>>(Wq, wqkvh, wqkvl, 0,        0.125f);  // fold 1/sqrt(64)
    split_qkv_k<<<13824, 256>>>(Wk, wqkvh, wqkvl, DDIM,     1.0f);
    split_qkv_k<<<13824, 256>>>(Wv, wqkvh, wqkvl, 2 * DDIM, 1.0f);
    bias_qkv_k<<<54, 256>>>(bq, bk, bv);
    split_plain_k<<< 3456, 256>>>((const float4*)Wo,  woh,  wol,  (long long)LNUM*DDIM*DDIM/4);
    split_plain_k<<<13824, 256>>>((const float4*)W1,  w1h,  w1l,  (long long)LNUM*DDIM*FDIM/4);
    split_plain_k<<<13824, 256>>>((const float4*)W2,  w2h,  w2l,  (long long)LNUM*FDIM*DDIM/4);
    split_plain_k<<<24000, 256>>>((const float4*)emb, embh, embl, (long long)VOC*DDIM/4);

    // x = emb[X] + pos
    embed_k<<<TTOK, 256>>>(X, emb, pos, x);

    // flash smem (R9 layout)
    const int FSMEM = (2 * FBR * FLQ + 2 * 2 * 2 * FBC * FLQ + 2 * FBR * FLQ) * 2
                      + FBR * FLS * 4;
    cudaFuncSetAttribute(flash_k, cudaFuncAttributeMaxDynamicSharedMemorySize, FSMEM);

    for (int l = 0; l < LNUM; l++) {
        // xn = LN1(x) (split)
        ln_k<<<TTOK, 256>>>(x, ln1s + l * DDIM, ln1b + l * DDIM, xnh, xnl);

        // fused qkv = xn @ Wqkv + bqkv -> split [T, 2304]  (128x128, 8 warps, 288 blk)
        run_gemm<128, 128, 32, 32, 64, 8, false, false, false, true>(
            xnh, xnl, wqkvh + (long long)l * DDIM * QKVN, wqkvl + (long long)l * DDIM * QKVN,
            bqkv + l * QKVN, nullptr, qkvh, qkvl,
            TTOK, QKVN, DDIM, DDIM, QKVN, QKVN);

        // fused causal attention -> ao (split)
        {
            dim3 fg(BAT * HNUM, SEQ / FBR);
            flash_k<<<fg, 256, FSMEM>>>(qkvh, qkvl, aoh, aol);
        }

        // x += ao @ Wo + bo   (64x64 tiles, 4 warps, 384 blocks)
        run_gemm<64, 64, 32, 32, 32, 4, false, false, true, false>(
            aoh, aol, woh + (long long)l * DDIM * DDIM, wol + (long long)l * DDIM * DDIM,
            bo + l * DDIM, x, nullptr, nullptr,
            TTOK, DDIM, DDIM, DDIM, DDIM, DDIM);

        // xn = LN2(x)
        ln_k<<<TTOK, 256>>>(x, ln2s + l * DDIM, ln2b + l * DDIM, xnh, xnl);

        // h1 = relu(xn @ W1 + b1) -> split   (128x128, 8 warps, 384 blocks)
        run_gemm<128, 128, 32, 32, 64, 8, false, true, false, true>(
            xnh, xnl, w1h + (long long)l * DDIM * FDIM, w1l + (long long)l * DDIM * FDIM,
            b1 + l * FDIM, nullptr, h1h, h1l,
            TTOK, FDIM, DDIM, DDIM, FDIM, FDIM);

        // x += h1 @ W2 + b2   (64x64 tiles, 4 warps, 384 blocks)
        run_gemm<64, 64, 32, 32, 32, 4, false, false, true, false>(
            h1h, h1l, w2h + (long long)l * FDIM * DDIM, w2l + (long long)l * FDIM * DDIM,
            b2 + l * DDIM, x, nullptr, nullptr,
            TTOK, DDIM, FDIM, FDIM, DDIM, DDIM);
    }

    // xn = LNf(x)
    ln_k<<<TTOK, 256>>>(x, lnfs, lnfb, xnh, xnl);

    // logits = xn @ emb^T + head_b  (128x128, 8 warps, SWAPXY: m fast, B L2 reuse)
    run_gemm<128, 128, 32, 32, 64, 8, true, false, false, false, true>(
        xnh, xnl, embh, embl, headb, out, nullptr, nullptr,
        TTOK, VOC, DDIM, DDIM, DDIM, VOC);
}

// round 14
// speedup vs baseline: 1.5926x; 1.0174x over previous
#include <cuda_runtime.h>
#include <cuda_bf16.h>
#include <mma.h>
#include <cstdint>

using namespace nvcuda;
typedef __nv_bfloat16 bf16;

#define LNUM 6
#define HNUM 12
#define DDIM 768
#define DHD  64
#define FDIM 3072
#define VOC  32000
#define SEQ  1024
#define BAT  2
#define TTOK (BAT*SEQ)
#define QKVN (3*DDIM)
#define EPS  1e-5f

// ---------------- scratch (static device globals; no allocation) ----------------
__device__ float g_x [TTOK*DDIM];
__device__ bf16 g_xnh[TTOK*DDIM],  g_xnl[TTOK*DDIM];
__device__ bf16 g_qkvh[(long long)TTOK*QKVN], g_qkvl[(long long)TTOK*QKVN];
__device__ bf16 g_aoh[TTOK*DDIM],  g_aol[TTOK*DDIM];
__device__ bf16 g_h1h[(long long)TTOK*FDIM], g_h1l[(long long)TTOK*FDIM];
// pre-split weights
__device__ bf16 g_wqkvh[(long long)LNUM*DDIM*QKVN], g_wqkvl[(long long)LNUM*DDIM*QKVN];
__device__ float g_bqkv[LNUM*QKVN];
__device__ bf16 g_woh[(long long)LNUM*DDIM*DDIM],  g_wol[(long long)LNUM*DDIM*DDIM];
__device__ bf16 g_w1h[(long long)LNUM*DDIM*FDIM],  g_w1l[(long long)LNUM*DDIM*FDIM];
__device__ bf16 g_w2h[(long long)LNUM*FDIM*DDIM],  g_w2l[(long long)LNUM*FDIM*DDIM];
__device__ bf16 g_embh[(long long)VOC*DDIM],       g_embl[(long long)VOC*DDIM];

// ---------------- helpers ----------------
__device__ __forceinline__ void split2(float v, bf16& h, bf16& l) {
    h = __float2bfloat16(v);
    l = __float2bfloat16(v - __bfloat162float(h));
}
__device__ __forceinline__ void cp16(bf16* dst, const bf16* src) {
    unsigned int d = (unsigned int)__cvta_generic_to_shared(dst);
    asm volatile("cp.async.cg.shared.global [%0], [%1], 16;" :: "r"(d), "l"(src));
}
__device__ __forceinline__ void cp_commit() { asm volatile("cp.async.commit_group;"); }
template<int N> __device__ __forceinline__ void cp_wait() {
    asm volatile("cp.async.wait_group %0;" :: "n"(N));
}
__device__ __forceinline__ float warp_sum(float v) {
    #pragma unroll
    for (int o = 16; o; o >>= 1) v += __shfl_xor_sync(0xffffffffu, v, o);
    return v;
}

// ---------------- weight pre-split kernels ----------------
__global__ void split_qkv_k(const float* __restrict__ src, bf16* __restrict__ hi,
                            bf16* __restrict__ lo, int coloff, float scale)
{
    long long idx = (long long)blockIdx.x * 256 + threadIdx.x;
    int kk = (int)(idx & (DHD - 1));
    long long t = idx >> 6;
    int d = (int)(t % DDIM); t /= DDIM;
    int h = (int)(t % HNUM);
    int l = (int)(t / HNUM);
    long long dst = ((long long)l * DDIM + d) * QKVN + coloff + h * DHD + kk;
    float v = src[idx] * scale;
    bf16 hh, ll; split2(v, hh, ll);
    hi[dst] = hh; lo[dst] = ll;
}

__global__ void bias_qkv_k(const float* __restrict__ bq, const float* __restrict__ bk,
                           const float* __restrict__ bv)
{
    int i = blockIdx.x * 256 + threadIdx.x;
    int col = i % QKVN, l = i / QKVN;
    float v;
    if (col < DDIM)            v = bq[l * DDIM + col] * 0.125f;
    else if (col < 2 * DDIM)   v = bk[l * DDIM + col - DDIM];
    else                       v = bv[l * DDIM + col - 2 * DDIM];
    g_bqkv[i] = v;
}

__global__ void split_plain_k(const float4* __restrict__ src, bf16* __restrict__ hi,
                              bf16* __restrict__ lo, long long n4)
{
    long long i = (long long)blockIdx.x * 256 + threadIdx.x;
    if (i >= n4) return;
    float4 v = src[i];
    bf16 h, l;
    __nv_bfloat162* h2 = (__nv_bfloat162*)hi;
    __nv_bfloat162* l2 = (__nv_bfloat162*)lo;
    __nv_bfloat162 ha, hb, la, lb;
    split2(v.x, h, l); ha.x = h; la.x = l;
    split2(v.y, h, l); ha.y = h; la.y = l;
    split2(v.z, h, l); hb.x = h; lb.x = l;
    split2(v.w, h, l); hb.y = h; lb.y = l;
    h2[2*i] = ha; h2[2*i+1] = hb;
    l2[2*i] = la; l2[2*i+1] = lb;
}

// ---------------- embedding ----------------
__global__ void embed_k(const int* __restrict__ X, const float* __restrict__ emb,
                        const float* __restrict__ pos, float* __restrict__ x)
{
    int t = blockIdx.x;
    int tok = X[t];
    int s = t % SEQ;
    const float* er = emb + (long long)tok * DDIM;
    const float* pr = pos + (long long)s * DDIM;
    float* xr = x + (long long)t * DDIM;
    for (int d = threadIdx.x; d < DDIM; d += blockDim.x)
        xr[d] = er[d] + pr[d];
}

// ---------------- layernorm -> split bf16 output (vectorized, reg-cached) --------
__global__ void ln_k(const float* __restrict__ x, const float* __restrict__ g,
                     const float* __restrict__ b, bf16* __restrict__ yh,
                     bf16* __restrict__ yl)
{
    int row = blockIdx.x;
    const float4* xr = (const float4*)(x + (long long)row * DDIM);   // 192 float4
    __nv_bfloat162* yhr = (__nv_bfloat162*)(yh + (long long)row * DDIM);
    __nv_bfloat162* ylr = (__nv_bfloat162*)(yl + (long long)row * DDIM);
    int tid = threadIdx.x;

    float4 v[1];
    float lv[4] = {0.f, 0.f, 0.f, 0.f};
    bool act = tid < 192;
    if (act) {
        v[0] = xr[tid];
        lv[0] = v[0].x; lv[1] = v[0].y; lv[2] = v[0].z; lv[3] = v[0].w;
    }
    float sum = lv[0] + lv[1] + lv[2] + lv[3];
    float sq  = lv[0]*lv[0] + lv[1]*lv[1] + lv[2]*lv[2] + lv[3]*lv[3];

    __shared__ float shs[8], shq[8];
    float s1 = warp_sum(sum), s2 = warp_sum(sq);
    int wid = tid >> 5, lane = tid & 31;
    if (lane == 0) { shs[wid] = s1; shq[wid] = s2; }
    __syncthreads();
    float ts = 0.f, tq = 0.f;
    #pragma unroll
    for (int w = 0; w < 8; w++) { ts += shs[w]; tq += shq[w]; }
    float mu = ts * (1.0f / DDIM);
    float var = tq * (1.0f / DDIM) - mu * mu;
    float r = rsqrtf(var + EPS);

    if (act) {
        const float4 gv = ((const float4*)g)[tid];
        const float4 bv = ((const float4*)b)[tid];
        float o0 = (lv[0] - mu) * r * gv.x + bv.x;
        float o1 = (lv[1] - mu) * r * gv.y + bv.y;
        float o2 = (lv[2] - mu) * r * gv.z + bv.z;
        float o3 = (lv[3] - mu) * r * gv.w + bv.w;
        bf16 h, l;
        __nv_bfloat162 ha, hb, la, lb;
        split2(o0, h, l); ha.x = h; la.x = l;
        split2(o1, h, l); ha.y = h; la.y = l;
        split2(o2, h, l); hb.x = h; lb.x = l;
        split2(o3, h, l); hb.y = h; lb.y = l;
        yhr[2*tid] = ha; yhr[2*tid+1] = hb;
        ylr[2*tid] = la; ylr[2*tid+1] = lb;
    }
}

// ---------------- fused causal flash attention: 64-row tiles, 2 CTAs/SM ----------
// smem: Q 18.4KB + K 36.9 + V 36.9 + union{S fp32, P hi/lo} 18.4 = 110.6KB.
#define F2R 64
#define FBC 64
#define FLQ 72     // bf16 row stride (pad)
#define FLS 68     // fp32 S/PV stride
__global__ void __launch_bounds__(256, 2) flash_k(
    const bf16* __restrict__ qkvh, const bf16* __restrict__ qkvl,
    bf16* __restrict__ aoh, bf16* __restrict__ aol)
{
    const int bh = blockIdx.x;
    const int b = bh / HNUM, h = bh - b * HNUM;
    const int m0 = (gridDim.y - 1 - blockIdx.y) * F2R;   // heavy blocks first
    const int hc = h * DHD;

    extern __shared__ char smraw[];
    bf16* sQh = (bf16*)smraw;                    // F2R*FLQ
    bf16* sQl = sQh + F2R * FLQ;
    bf16* sK  = sQl + F2R * FLQ;                 // 2 stages * 2(hi/lo) * FBC*FLQ
    bf16* sV  = sK + 2 * 2 * FBC * FLQ;
    char* U   = (char*)(sV + 2 * 2 * FBC * FLQ); // union region
    float* sS = (float*)U;                       // F2R*FLS fp32 (17408B)
    bf16* sPh = (bf16*)U;                        // F2R*FLQ (aliases sS)
    bf16* sPl = sPh + F2R * FLQ;

    const int tid = threadIdx.x;
    const int w = tid >> 5;
    const int warp_m = (w & 1) * 32;             // 2 warp-rows (64)
    const int warp_n = (w >> 1) * 16;            // 4 warp-cols (64)

    const long long qrow0 = (long long)(b * SEQ + m0);

    // ---- stage Q (64x64 hi/lo): 512 chunks per tensor ----
    #pragma unroll
    for (int it = 0; it < 2; it++) {
        int v = tid + it * 256;
        int row = v >> 3, c8 = v & 7;
        long long g = (qrow0 + row) * QKVN + hc + c8 * 8;
        cp16(sQh + row * FLQ + c8 * 8, qkvh + g);
        cp16(sQl + row * FLQ + c8 * 8, qkvl + g);
    }
    cp_commit();

    auto load_kv = [&](int jt, int s) {
        const long long krow0 = (long long)(b * SEQ + jt * FBC);
        bf16* kH = sK + s * 2 * FBC * FLQ;
        bf16* kL = kH + FBC * FLQ;
        bf16* vH = sV + s * 2 * FBC * FLQ;
        bf16* vL = vH + FBC * FLQ;
        #pragma unroll
        for (int it = 0; it < 2; it++) {
            int v = tid + it * 256;
            int row = v >> 3, c8 = v & 7;
            long long gk = (krow0 + row) * QKVN + DDIM + hc + c8 * 8;
            long long gv = (krow0 + row) * QKVN + 2 * DDIM + hc + c8 * 8;
            cp16(kH + row * FLQ + c8 * 8, qkvh + gk);
            cp16(kL + row * FLQ + c8 * 8, qkvl + gk);
            cp16(vH + row * FLQ + c8 * 8, qkvh + gv);
            cp16(vL + row * FLQ + c8 * 8, qkvl + gv);
        }
    };

    const int nj = m0 / FBC + 1;                 // keys up to m0+63
    load_kv(0, 0);
    cp_commit();

    // softmax state: 4 threads per row; thread owns 16 cols
    const int row = tid >> 2;
    const int col0 = (tid & 3) * 16;
    float Oreg[16];
    #pragma unroll
    for (int c = 0; c < 16; c++) Oreg[c] = 0.f;
    float mrow = -1e30f, lrow = 0.f;

    for (int jt = 0; jt < nj; jt++) {
        const int s = jt & 1;
        if (jt + 1 < nj) { load_kv(jt + 1, s ^ 1); cp_commit(); cp_wait<1>(); }
        else             cp_wait<0>();
        __syncthreads();                          // (1) K/V (and Q) visible

        bf16* kH = sK + s * 2 * FBC * FLQ;
        bf16* kL = kH + FBC * FLQ;
        bf16* vH = sV + s * 2 * FBC * FLQ;
        bf16* vL = vH + FBC * FLQ;

        // ---- S = Q K^T (3-term) -> sS ----
        {
            wmma::fragment<wmma::accumulator, 16, 16, 16, float> sacc[2];
            #pragma unroll
            for (int i = 0; i < 2; i++) wmma::fill_fragment(sacc[i], 0.f);
            #pragma unroll
            for (int kk = 0; kk < 4; kk++) {
                wmma::fragment<wmma::matrix_a, 16, 16, 16, bf16, wmma::row_major> ahi[2], alo[2];
                #pragma unroll
                for (int i = 0; i < 2; i++) {
                    int off = (warp_m + i * 16) * FLQ + kk * 16;
                    wmma::load_matrix_sync(ahi[i], sQh + off, FLQ);
                    wmma::load_matrix_sync(alo[i], sQl + off, FLQ);
                }
                wmma::fragment<wmma::matrix_b, 16, 16, 16, bf16, wmma::col_major> bhi, blo;
                int off = warp_n * FLQ + kk * 16;
                wmma::load_matrix_sync(bhi, kH + off, FLQ);
                wmma::load_matrix_sync(blo, kL + off, FLQ);
                #pragma unroll
                for (int i = 0; i < 2; i++) {
                    wmma::mma_sync(sacc[i], ahi[i], bhi, sacc[i]);
                    wmma::mma_sync(sacc[i], ahi[i], blo, sacc[i]);
                    wmma::mma_sync(sacc[i], alo[i], bhi, sacc[i]);
                }
            }
            #pragma unroll
            for (int i = 0; i < 2; i++)
                wmma::store_matrix_sync(sS + (warp_m + i * 16) * FLS + warp_n,
                                        sacc[i], FLS, wmma::mem_row_major);
        }
        __syncthreads();                          // (2) S visible

        // ---- online softmax (read all S into regs; P aliases S) ----
        float sv[16];
        {
            const int jbase = jt * FBC;
            const int rlimit = m0 + row;
            float bmax = -1e30f;
            #pragma unroll
            for (int c = 0; c < 16; c++) {
                float vv = sS[row * FLS + col0 + c];
                if (jbase + col0 + c > rlimit) vv = -1e30f;
                sv[c] = vv;
                bmax = fmaxf(bmax, vv);
            }
            bmax = fmaxf(bmax, __shfl_xor_sync(0xffffffffu, bmax, 1));
            bmax = fmaxf(bmax, __shfl_xor_sync(0xffffffffu, bmax, 2));
            float m_new = fmaxf(mrow, bmax);
            float alpha = __expf(mrow - m_new);
            float psum = 0.f;
            #pragma unroll
            for (int c = 0; c < 16; c++) {
                float e = __expf(sv[c] - m_new);
                sv[c] = e;
                psum += e;
            }
            psum += __shfl_xor_sync(0xffffffffu, psum, 1);
            psum += __shfl_xor_sync(0xffffffffu, psum, 2);
            lrow = lrow * alpha + psum;
            mrow = m_new;
            #pragma unroll
            for (int c = 0; c < 16; c++) Oreg[c] *= alpha;
        }
        __syncthreads();                          // (3) all S reads done (alias)
        #pragma unroll
        for (int c = 0; c < 16; c++) {
            bf16 hh, ll; split2(sv[c], hh, ll);
            sPh[row * FLQ + col0 + c] = hh;       // overwrites S region
            sPl[row * FLQ + col0 + c] = ll;
        }
        __syncthreads();                          // (4) P visible

        // ---- PV = P V (3-term) ----
        {
            wmma::fragment<wmma::accumulator, 16, 16, 16, float> pv[2];
            #pragma unroll
            for (int i = 0; i < 2; i++) wmma::fill_fragment(pv[i], 0.f);
            #pragma unroll
            for (int kk = 0; kk < 4; kk++) {
                wmma::fragment<wmma::matrix_a, 16, 16, 16, bf16, wmma::row_major> phi[2], plo[2];
                #pragma unroll
                for (int i = 0; i < 2; i++) {
                    int off = (warp_m + i * 16) * FLQ + kk * 16;
                    wmma::load_matrix_sync(phi[i], sPh + off, FLQ);
                    wmma::load_matrix_sync(plo[i], sPl + off, FLQ);
                }
                wmma::fragment<wmma::matrix_b, 16, 16, 16, bf16, wmma::row_major> vhi, vlo;
                int off = (kk * 16) * FLQ + warp_n;
                wmma::load_matrix_sync(vhi, vH + off, FLQ);
                wmma::load_matrix_sync(vlo, vL + off, FLQ);
                #pragma unroll
                for (int i = 0; i < 2; i++) {
                    wmma::mma_sync(pv[i], phi[i], vhi, pv[i]);
                    wmma::mma_sync(pv[i], phi[i], vlo, pv[i]);
                    wmma::mma_sync(pv[i], plo[i], vhi, pv[i]);
                }
            }
            __syncthreads();                      // (5) all P reads done (alias)
            #pragma unroll
            for (int i = 0; i < 2; i++)
                wmma::store_matrix_sync(sS + (warp_m + i * 16) * FLS + warp_n,
                                        pv[i], FLS, wmma::mem_row_major);
        }
        __syncthreads();                          // (6) PV visible

        #pragma unroll
        for (int c = 0; c < 16; c++) Oreg[c] += sS[row * FLS + col0 + c];
    }

    const float inv = 1.0f / lrow;
    const long long obase = (qrow0 + row) * DDIM + hc + col0;
    #pragma unroll
    for (int c = 0; c < 16; c++) {
        bf16 hh, ll; split2(Oreg[c] * inv, hh, ll);
        aoh[obase + c] = hh;
        aol[obase + c] = ll;
    }
}

// ---------------- bf16-split tensor-core GEMM, cp.async double-buffered ------------
// NW = warps/block (4 or 8). SWAPXY: read m from blockIdx.x (L2 reuse of B).
template<int BM, int BN, int BK, int WM, int WN, int NW,
         bool TRANSB, bool RELU, bool RESID, bool OSPLIT, bool SWAPXY>
__global__ void __launch_bounds__(NW * 32, (NW == 8) ? 2 : 4) gemm_tc(
    const bf16* __restrict__ Ahig, const bf16* __restrict__ Alog,
    const bf16* __restrict__ Bhig, const bf16* __restrict__ Blog,
    const float* __restrict__ biasg,
    float* __restrict__ Cg, bf16* __restrict__ Chig, bf16* __restrict__ Clog,
    int K, int lda, int ldb, int ldc)
{
    constexpr int NT = NW * 32;
    constexpr int LDA = BK + 8;
    constexpr int BROWS = TRANSB ? BN : BK;
    constexpr int LDB = TRANSB ? (BK + 8) : (BN + 8);
    constexpr int A_EL = BM * LDA;
    constexpr int B_EL = BROWS * LDB;
    constexpr int MI = WM / 16, NI = WN / 16;
    static_assert((BM / WM) * (BN / WN) == NW, "warp layout");

    const int bxn = SWAPXY ? blockIdx.y : blockIdx.x;
    const int bym = SWAPXY ? blockIdx.x : blockIdx.y;
    const int m0 = bym * BM;
    const int n0 = bxn * BN;

    extern __shared__ char smraw[];
    bf16* sAhi = (bf16*)smraw;
    bf16* sAlo = sAhi + 2 * A_EL;
    bf16* sBhi = sAlo + 2 * A_EL;
    bf16* sBlo = sBhi + 2 * B_EL;
    float* stg = (float*)smraw;    // aliases A buffers; used only after final sync

    const int tid = threadIdx.x;
    const int w = tid >> 5, lane = tid & 31;
    const int warp_m = (w / (BN / WN)) * WM;
    const int warp_n = (w % (BN / WN)) * WN;

    wmma::fragment<wmma::accumulator, 16, 16, 16, float> acc[MI][NI];
    #pragma unroll
    for (int i = 0; i < MI; i++)
        #pragma unroll
        for (int j = 0; j < NI; j++) wmma::fill_fragment(acc[i][j], 0.f);

    const int nk = K / BK;

    auto load_stage = [&](int kt, int s) {
        const int k0 = kt * BK;
        constexpr int CA = BM * BK / 8;
        #pragma unroll
        for (int it = 0; it < CA / NT; it++) {
            int v = tid + it * NT;
            int row = v / (BK / 8), c = v % (BK / 8);
            long long g = (long long)(m0 + row) * lda + k0 + c * 8;
            int sm = s * A_EL + row * LDA + c * 8;
            cp16(sAhi + sm, Ahig + g);
            cp16(sAlo + sm, Alog + g);
        }
        constexpr int CB = BK * BN / 8;
        #pragma unroll
        for (int it = 0; it < CB / NT; it++) {
            int v = tid + it * NT;
            if (!TRANSB) {
                int row = v / (BN / 8), c = v % (BN / 8);
                long long g = (long long)(k0 + row) * ldb + n0 + c * 8;
                int sm = s * B_EL + row * LDB + c * 8;
                cp16(sBhi + sm, Bhig + g);
                cp16(sBlo + sm, Blog + g);
            } else {
                int row = v / (BK / 8), c = v % (BK / 8);
                long long g = (long long)(n0 + row) * ldb + k0 + c * 8;
                int sm = s * B_EL + row * LDB + c * 8;
                cp16(sBhi + sm, Bhig + g);
                cp16(sBlo + sm, Blog + g);
            }
        }
    };

    load_stage(0, 0);
    cp_commit();

    for (int kt = 0; kt < nk; kt++) {
        const int s = kt & 1;
        if (kt + 1 < nk) { load_stage(kt + 1, s ^ 1); cp_commit(); cp_wait<1>(); }
        else             cp_wait<0>();
        __syncthreads();

        #pragma unroll
        for (int kk = 0; kk < BK / 16; kk++) {
            wmma::fragment<wmma::matrix_a, 16, 16, 16, bf16, wmma::row_major> ahi[MI], alo[MI];
            #pragma unroll
            for (int i = 0; i < MI; i++) {
                int off = s * A_EL + (warp_m + i * 16) * LDA + kk * 16;
                wmma::load_matrix_sync(ahi[i], sAhi + off, LDA);
                wmma::load_matrix_sync(alo[i], sAlo + off, LDA);
            }
            #pragma unroll
            for (int j = 0; j < NI; j++) {
                if constexpr (TRANSB) {
                    wmma::fragment<wmma::matrix_b, 16, 16, 16, bf16, wmma::col_major> bhi, blo;
                    int off = s * B_EL + (warp_n + j * 16) * LDB + kk * 16;
                    wmma::load_matrix_sync(bhi, sBhi + off, LDB);
                    wmma::load_matrix_sync(blo, sBlo + off, LDB);
                    #pragma unroll
                    for (int i = 0; i < MI; i++) {
                        wmma::mma_sync(acc[i][j], ahi[i], bhi, acc[i][j]);
                        wmma::mma_sync(acc[i][j], ahi[i], blo, acc[i][j]);
                        wmma::mma_sync(acc[i][j], alo[i], bhi, acc[i][j]);
                    }
                } else {
                    wmma::fragment<wmma::matrix_b, 16, 16, 16, bf16, wmma::row_major> bhi, blo;
                    int off = s * B_EL + (kk * 16) * LDB + warp_n + j * 16;
                    wmma::load_matrix_sync(bhi, sBhi + off, LDB);
                    wmma::load_matrix_sync(blo, sBlo + off, LDB);
                    #pragma unroll
                    for (int i = 0; i < MI; i++) {
                        wmma::mma_sync(acc[i][j], ahi[i], bhi, acc[i][j]);
                        wmma::mma_sync(acc[i][j], ahi[i], blo, acc[i][j]);
                        wmma::mma_sync(acc[i][j], alo[i], bhi, acc[i][j]);
                    }
                }
            }
        }
        __syncthreads();
    }

    // ---- epilogue via per-warp smem staging (aliased onto A buffers) ----
    #pragma unroll
    for (int i = 0; i < MI; i++) {
        #pragma unroll
        for (int j = 0; j < NI; j++) {
            wmma::store_matrix_sync(stg + w * 256, acc[i][j], 16, wmma::mem_row_major);
            __syncwarp();
            #pragma unroll
            for (int e = 0; e < 8; e++) {
                int idx = lane + 32 * e;
                int r = idx >> 4, c = idx & 15;
                int m = m0 + warp_m + i * 16 + r;
                int n = n0 + warp_n + j * 16 + c;
                long long cidx = (long long)m * ldc + n;
                float v = stg[w * 256 + idx];
                if (biasg) v += __ldg(biasg + n);
                if (RESID) v += Cg[cidx];
                if (RELU)  v = fmaxf(v, 0.f);
                if (OSPLIT) { bf16 h, l; split2(v, h, l); Chig[cidx] = h; Clog[cidx] = l; }
                else        Cg[cidx] = v;
            }
            __syncwarp();
        }
    }
}

// ---------------- host launcher ----------------
template<int BM, int BN, int BK, int WM, int WN, int NW,
         bool TRANSB, bool RELU, bool RESID, bool OSPLIT, bool SWAPXY = false>
static void run_gemm(const bf16* Ahi, const bf16* Alo, const bf16* Bhi, const bf16* Blo,
                     const float* bias, float* C, bf16* Chi, bf16* Clo,
                     int M, int N, int K, int lda, int ldb, int ldc)
{
    constexpr int LDA = BK + 8;
    constexpr int BROWS = TRANSB ? BN : BK;
    constexpr int LDB = TRANSB ? (BK + 8) : (BN + 8);
    constexpr size_t SB = (size_t)8 * BM * LDA + (size_t)8 * BROWS * LDB;
    auto fn = gemm_tc<BM, BN, BK, WM, WN, NW, TRANSB, RELU, RESID, OSPLIT, SWAPXY>;
    cudaFuncSetAttribute(fn, cudaFuncAttributeMaxDynamicSharedMemorySize, (int)SB);
    dim3 grid = SWAPXY ? dim3(M / BM, N / BN) : dim3(N / BN, M / BM);
    fn<<<grid, NW * 32, SB>>>(Ahi, Alo, Bhi, Blo, bias, C, Chi, Clo, K, lda, ldb, ldc);
}

extern "C" void kernel_launch(void* const* d_in, const int* in_sizes, int n_in,
                              void* d_out, int out_size)
{
    const int*   X      = (const int*)  d_in[0];
    const float* emb    = (const float*)d_in[1];
    const float* pos    = (const float*)d_in[2];
    const float* Wq     = (const float*)d_in[3];
    const float* bq     = (const float*)d_in[4];
    const float* Wk     = (const float*)d_in[5];
    const float* bk     = (const float*)d_in[6];
    const float* Wv     = (const float*)d_in[7];
    const float* bv     = (const float*)d_in[8];
    const float* Wo     = (const float*)d_in[9];
    const float* bo     = (const float*)d_in[10];
    const float* ln1s   = (const float*)d_in[11];
    const float* ln1b   = (const float*)d_in[12];
    const float* ln2s   = (const float*)d_in[13];
    const float* ln2b   = (const float*)d_in[14];
    const float* W1     = (const float*)d_in[15];
    const float* b1     = (const float*)d_in[16];
    const float* W2     = (const float*)d_in[17];
    const float* b2     = (const float*)d_in[18];
    const float* lnfs   = (const float*)d_in[19];
    const float* lnfb   = (const float*)d_in[20];
    const float* headb  = (const float*)d_in[21];
    float* out = (float*)d_out;

    float *x, *bqkv;
    bf16 *xnh, *xnl, *qkvh, *qkvl, *aoh, *aol, *h1h, *h1l;
    bf16 *wqkvh, *wqkvl, *woh, *wol, *w1h, *w1l, *w2h, *w2l, *embh, *embl;
    cudaGetSymbolAddress((void**)&x,     g_x);
    cudaGetSymbolAddress((void**)&xnh,   g_xnh);
    cudaGetSymbolAddress((void**)&xnl,   g_xnl);
    cudaGetSymbolAddress((void**)&qkvh,  g_qkvh);
    cudaGetSymbolAddress((void**)&qkvl,  g_qkvl);
    cudaGetSymbolAddress((void**)&aoh,   g_aoh);
    cudaGetSymbolAddress((void**)&aol,   g_aol);
    cudaGetSymbolAddress((void**)&h1h,   g_h1h);
    cudaGetSymbolAddress((void**)&h1l,   g_h1l);
    cudaGetSymbolAddress((void**)&wqkvh, g_wqkvh);
    cudaGetSymbolAddress((void**)&wqkvl, g_wqkvl);
    cudaGetSymbolAddress((void**)&bqkv,  g_bqkv);
    cudaGetSymbolAddress((void**)&woh,   g_woh);
    cudaGetSymbolAddress((void**)&wol,   g_wol);
    cudaGetSymbolAddress((void**)&w1h,   g_w1h);
    cudaGetSymbolAddress((void**)&w1l,   g_w1l);
    cudaGetSymbolAddress((void**)&w2h,   g_w2h);
    cudaGetSymbolAddress((void**)&w2l,   g_w2l);
    cudaGetSymbolAddress((void**)&embh,  g_embh);
    cudaGetSymbolAddress((void**)&embl,  g_embl);

    // ---- weight pre-split (once per call) ----
    split_qkv_k<<<13824, 256>>>(Wq, wqkvh, wqkvl, 0,        0.125f);  // fold 1/sqrt(64)
    split_qkv_k<<<13824, 256>>>(Wk, wqkvh, wqkvl, DDIM,     1.0f);
    split_qkv_k<<<13824, 256>>>(Wv, wqkvh, wqkvl, 2 * DDIM, 1.0f);
    bias_qkv_k<<<54, 256>>>(bq, bk, bv);
    split_plain_k<<< 3456, 256>>>((const float4*)Wo,  woh,  wol,  (long long)LNUM*DDIM*DDIM/4);
    split_plain_k<<<13824, 256>>>((const float4*)W1,  w1h,  w1l,  (long long)LNUM*DDIM*FDIM/4);
    split_plain_k<<<13824, 256>>>((const float4*)W2,  w2h,  w2l,  (long long)LNUM*FDIM*DDIM/4);
    split_plain_k<<<24000, 256>>>((const float4*)emb, embh, embl, (long long)VOC*DDIM/4);

    // x = emb[X] + pos
    embed_k<<<TTOK, 256>>>(X, emb, pos, x);

    // flash smem: Q + K(2st) + V(2st) + union(S, P hi/lo)
    const int FSMEM = (2 * F2R * FLQ + 2 * 2 * 2 * FBC * FLQ) * 2
                      + 2 * F2R * FLQ * 2;   // union sized by larger member (P)
    cudaFuncSetAttribute(flash_k, cudaFuncAttributeMaxDynamicSharedMemorySize, FSMEM);

    for (int l = 0; l < LNUM; l++) {
        // xn = LN1(x) (split)
        ln_k<<<TTOK, 256>>>(x, ln1s + l * DDIM, ln1b + l * DDIM, xnh, xnl);

        // fused qkv = xn @ Wqkv + bqkv -> split [T, 2304]  (128x128, 8 warps, 288 blk)
        run_gemm<128, 128, 32, 32, 64, 8, false, false, false, true>(
            xnh, xnl, wqkvh + (long long)l * DDIM * QKVN, wqkvl + (long long)l * DDIM * QKVN,
            bqkv + l * QKVN, nullptr, qkvh, qkvl,
            TTOK, QKVN, DDIM, DDIM, QKVN, QKVN);

        // fused causal attention -> ao (split); 64-row tiles, 2 CTAs/SM
        {
            dim3 fg(BAT * HNUM, SEQ / F2R);
            flash_k<<<fg, 256, FSMEM>>>(qkvh, qkvl, aoh, aol);
        }

        // x += ao @ Wo + bo   (64x64 tiles, 4 warps, 384 blocks)
        run_gemm<64, 64, 32, 32, 32, 4, false, false, true, false>(
            aoh, aol, woh + (long long)l * DDIM * DDIM, wol + (long long)l * DDIM * DDIM,
            bo + l * DDIM, x, nullptr, nullptr,
            TTOK, DDIM, DDIM, DDIM, DDIM, DDIM);

        // xn = LN2(x)
        ln_k<<<TTOK, 256>>>(x, ln2s + l * DDIM, ln2b + l * DDIM, xnh, xnl);

        // h1 = relu(xn @ W1 + b1) -> split   (128x128, 8 warps, 384 blocks)
        run_gemm<128, 128, 32, 32, 64, 8, false, true, false, true>(
            xnh, xnl, w1h + (long long)l * DDIM * FDIM, w1l + (long long)l * DDIM * FDIM,
            b1 + l * FDIM, nullptr, h1h, h1l,
            TTOK, FDIM, DDIM, DDIM, FDIM, FDIM);

        // x += h1 @ W2 + b2   (64x64 tiles, 4 warps, 384 blocks)
        run_gemm<64, 64, 32, 32, 32, 4, false, false, true, false>(
            h1h, h1l, w2h + (long long)l * FDIM * DDIM, w2l + (long long)l * FDIM * DDIM,
            b2 + l * DDIM, x, nullptr, nullptr,
            TTOK, DDIM, FDIM, FDIM, DDIM, DDIM);
    }

    // xn = LNf(x)
    ln_k<<<TTOK, 256>>>(x, lnfs, lnfb, xnh, xnl);

    // logits = xn @ emb^T + head_b  (128x128, 8 warps, SWAPXY: m fast, B L2 reuse)
    run_gemm<128, 128, 32, 32, 64, 8, true, false, false, false, true>(
        xnh, xnl, embh, embl, headb, out, nullptr, nullptr,
        TTOK, VOC, DDIM, DDIM, DDIM, VOC);
}